// round 4
// baseline (speedup 1.0000x reference)
#include <cuda_runtime.h>
#include <cuda_bf16.h>
#include <math.h>

#define S_N 10000
#define R_N 16
#define FD 128
#define H_N 4
#define B_N 2048
#define C_N 16
#define NEG (-9e15f)
#define SW 313        // ceil(S/32) words per bitmask row
#define SP 10112      // 79*128, padded S for W matrix
#define NCH 158       // vpart chunks (79 tiles x 2 halves)

// ---------------- scratch (device globals; no allocation allowed) ----------
__device__ float g_h1[H_N * R_N * FD];             // [H][R][F]
__device__ float g_h1a[H_N * R_N];                 // h1 . a[:F]
__device__ float g_h2[(size_t)H_N * S_N * FD];     // [H][S][F]
__device__ __nv_bfloat16 g_h2sb[H_N * B_N * FD];   // gathered h2[src], bf16
__device__ unsigned g_cbits[B_N * SW];
__device__ unsigned g_pbits[B_N * SW];
__device__ float2 g_inv2[B_N];                     // (1/degc, 1/degp)
__device__ __nv_bfloat16 g_wb[(size_t)B_N * SP];   // W[b][s] bf16 (zero-padded)
__device__ float g_att[H_N * S_N * R_N];           // inter attention
__device__ float g_vpart[NCH * H_N * R_N * FD];    // partial sums for v
__device__ float g_v[H_N * R_N * FD];              // post-BN, lrelu'd v
__device__ float g_u[(size_t)H_N * S_N * FD];      // pre-BN u
__device__ float g_upsum[79 * H_N * FD];
__device__ float g_upsq[79 * H_N * FD];
__device__ float g_alpha[H_N * FD];
__device__ float g_beta[H_N * FD];

__device__ __forceinline__ float lrelu(float x) { return x > 0.f ? x : 0.2f * x; }
__device__ __forceinline__ float elu(float x)   { return x > 0.f ? x : expm1f(x); }
__device__ __forceinline__ unsigned su(const void* p) {
    return (unsigned)__cvta_generic_to_shared(p);
}
__device__ __forceinline__ void mma_bf16(float c[4], const unsigned a[4], const unsigned b[2]) {
    asm volatile(
        "mma.sync.aligned.m16n8k16.row.col.f32.bf16.bf16.f32 "
        "{%0,%1,%2,%3},{%4,%5,%6,%7},{%8,%9},{%0,%1,%2,%3};"
        : "+f"(c[0]), "+f"(c[1]), "+f"(c[2]), "+f"(c[3])
        : "r"(a[0]), "r"(a[1]), "r"(a[2]), "r"(a[3]), "r"(b[0]), "r"(b[1]));
}
__device__ __forceinline__ void ldmx4t(unsigned& r0, unsigned& r1, unsigned& r2, unsigned& r3,
                                       unsigned addr) {
    asm volatile("ldmatrix.sync.aligned.m8n8.x4.trans.shared.b16 {%0,%1,%2,%3},[%4];"
                 : "=r"(r0), "=r"(r1), "=r"(r2), "=r"(r3) : "r"(addr));
}
#define CP16(d, s) asm volatile("cp.async.cg.shared.global [%0],[%1],16;" ::"r"(d), "l"(s))
#define CPCOMMIT   asm volatile("cp.async.commit_group;")
#define CPWAIT0    asm volatile("cp.async.wait_group 0;")

// ---------------- K1: h1 = Rfeat @ W1[h], h1a = h1 . a[:F] ------------------
__global__ void k1_h1(const float* __restrict__ Rfeat, const float* __restrict__ W1,
                      const float* __restrict__ a) {
    int h = blockIdx.x / R_N, r = blockIdx.x % R_N, f = threadIdx.x;
    const float* w  = W1 + (size_t)h * FD * FD;
    const float* rf = Rfeat + r * FD;
    float acc = 0.f;
    #pragma unroll 8
    for (int k = 0; k < FD; k++) acc = fmaf(rf[k], w[k * FD + f], acc);
    g_h1[(h * R_N + r) * FD + f] = acc;
    __shared__ float sh[128];
    sh[f] = acc * a[h * 2 * FD + f];
    __syncthreads();
    for (int st = 64; st > 0; st >>= 1) {
        if (f < st) sh[f] += sh[f + st];
        __syncthreads();
    }
    if (f == 0) g_h1a[h * R_N + r] = sh[0];
}

// ---------------- K2: h2 = Sfeat @ W2[h]  (broadcast-smem register blocked) -
__global__ __launch_bounds__(256) void k2_h2(const float* __restrict__ Sfeat,
                                             const float* __restrict__ W2) {
    const int h = blockIdx.y;
    const int s0 = blockIdx.x * 64;
    const int tid = threadIdx.x;
    const int tx = tid & 31;        // f = 4*tx
    const int ty = tid >> 5;        // s group of 8
    __shared__ float sf[FD][68];    // [k][s], stride 68 (16B aligned rows)
    for (int i = tid; i < 64 * FD; i += 256) {
        int sl = i >> 7, k = i & 127;
        int s = s0 + sl;
        sf[k][sl] = (s < S_N) ? Sfeat[(size_t)s * FD + k] : 0.f;
    }
    __syncthreads();
    float acc[8][4];
    #pragma unroll
    for (int i = 0; i < 8; i++)
        #pragma unroll
        for (int j = 0; j < 4; j++) acc[i][j] = 0.f;
    const float4* w4 = (const float4*)(W2 + (size_t)h * FD * FD);
    #pragma unroll 4
    for (int k = 0; k < FD; k++) {
        float4 wv = w4[k * 32 + tx];
        float4 sa = *(const float4*)&sf[k][ty * 8];
        float4 sb = *(const float4*)&sf[k][ty * 8 + 4];
        float sv[8] = {sa.x, sa.y, sa.z, sa.w, sb.x, sb.y, sb.z, sb.w};
        #pragma unroll
        for (int i = 0; i < 8; i++) {
            acc[i][0] = fmaf(sv[i], wv.x, acc[i][0]);
            acc[i][1] = fmaf(sv[i], wv.y, acc[i][1]);
            acc[i][2] = fmaf(sv[i], wv.z, acc[i][2]);
            acc[i][3] = fmaf(sv[i], wv.w, acc[i][3]);
        }
    }
    #pragma unroll
    for (int i = 0; i < 8; i++) {
        int s = s0 + ty * 8 + i;
        if (s < S_N) {
            float4 o = make_float4(acc[i][0], acc[i][1], acc[i][2], acc[i][3]);
            *(float4*)&g_h2[((size_t)h * S_N + s) * FD + tx * 4] = o;
        }
    }
}

// ---------------- K3: bitpack gathered adjacency rows + degrees -------------
__global__ void k3_bits(const int* __restrict__ city, const int* __restrict__ prov,
                        const int* __restrict__ src) {
    int b = blockIdx.x;
    int n = src[b];
    const int* crow = city + (size_t)n * S_N;
    const int* prow = prov + (size_t)n * S_N;
    int lane = threadIdx.x & 31, wid = threadIdx.x >> 5;  // 8 warps
    int degc = 0, degp = 0;
    for (int w = wid; w < SW; w += 8) {
        int s = w * 32 + lane;
        bool inb = s < S_N;
        int cv = inb ? crow[s] : 0;
        int pv = inb ? prow[s] : 0;
        unsigned cm = __ballot_sync(0xffffffffu, cv > 0);
        unsigned pm = __ballot_sync(0xffffffffu, pv > 0);
        if (lane == 0) {
            g_cbits[b * SW + w] = cm;
            g_pbits[b * SW + w] = pm;
            degc += __popc(cm);
            degp += __popc(pm);
        }
    }
    __shared__ int sdc[8], sdp[8];
    if (lane == 0) { sdc[wid] = degc; sdp[wid] = degp; }
    __syncthreads();
    if (threadIdx.x == 0) {
        int dc = 0, dp = 0;
        for (int i = 0; i < 8; i++) { dc += sdc[i]; dp += sdp[i]; }
        g_inv2[b] = make_float2(dc > 0 ? 1.f / (float)dc : 0.f,
                                dp > 0 ? 1.f / (float)dp : 0.f);
    }
}

// ---------------- K3w: materialize W[b][s] in bf16 ---------------------------
__global__ void k3w_wb() {
    int b = blockIdx.x;
    float2 iv = g_inv2[b];
    const unsigned* cb = g_cbits + (size_t)b * SW;
    const unsigned* pb = g_pbits + (size_t)b * SW;
    __nv_bfloat16* wrow = g_wb + (size_t)b * SP;
    for (int s = threadIdx.x; s < SP; s += blockDim.x) {
        float v = 0.f;
        if (s < S_N) {
            unsigned cw = cb[s >> 5], pw = pb[s >> 5];
            int bit = s & 31;
            v = ((cw >> bit) & 1u) ? iv.x : 0.f;
            if ((pw >> bit) & 1u) v += iv.y;
        }
        wrow[s] = __float2bfloat16(v);
    }
}

// ---------------- K3b: gather h2s = h2[src] (bf16) --------------------------
__global__ void k3b_gather(const int* __restrict__ src) {
    int h = blockIdx.y, b = blockIdx.x, f = threadIdx.x;
    int n = src[b];
    g_h2sb[((h * B_N) + b) * FD + f] =
        __float2bfloat16(g_h2[((size_t)h * S_N + n) * FD + f]);
}

// ---------------- K45: inter attention + v partials (fused) ------------------
__global__ __launch_bounds__(256) void k45_attv(const int* __restrict__ inter,
                                                const float* __restrict__ a) {
    const int h = blockIdx.y, tile = blockIdx.x, s0 = tile * 128;
    const int tid = threadIdx.x, lane = tid & 31, w = tid >> 5;
    __shared__ float attS[128][17];
    const float* a2 = a + h * 2 * FD + FD;
    float a2v[4];
    #pragma unroll
    for (int i = 0; i < 4; i++) a2v[i] = a2[lane + 32 * i];
    // phase 1: attention rows
    for (int it = 0; it < 16; it++) {
        int sl = w * 16 + it;
        int s = s0 + sl;
        if (s < S_N) {
            const float* row = &g_h2[((size_t)h * S_N + s) * FD];
            float d = 0.f;
            #pragma unroll
            for (int i = 0; i < 4; i++) d = fmaf(row[lane + 32 * i], a2v[i], d);
            #pragma unroll
            for (int o = 16; o > 0; o >>= 1) d += __shfl_xor_sync(0xffffffffu, d, o);
            float z = NEG;
            if (lane < R_N && inter[s * R_N + lane] > 0)
                z = lrelu(d + g_h1a[h * R_N + lane]);
            float mx = z;
            #pragma unroll
            for (int o = 8; o > 0; o >>= 1) mx = fmaxf(mx, __shfl_xor_sync(0xffffffffu, mx, o));
            float ex = (lane < R_N) ? expf(z - mx) : 0.f;
            float sm = ex;
            #pragma unroll
            for (int o = 8; o > 0; o >>= 1) sm += __shfl_xor_sync(0xffffffffu, sm, o);
            if (lane < R_N) {
                float av = ex / sm;
                attS[sl][lane] = av;
                g_att[((h * S_N) + s) * R_N + lane] = av;
            }
        } else if (lane < R_N) {
            attS[sl][lane] = 0.f;
        }
    }
    __syncthreads();
    // phase 2: vpart for this half-chunk
    const int f = tid & 127, half = tid >> 7;
    float acc[R_N];
    #pragma unroll
    for (int r = 0; r < R_N; r++) acc[r] = 0.f;
    const int base = half * 64;
    for (int si = 0; si < 64; si++) {
        int s = s0 + base + si;
        if (s >= S_N) break;
        float v = g_h2[((size_t)h * S_N + s) * FD + f];
        #pragma unroll
        for (int r = 0; r < R_N; r++) acc[r] = fmaf(attS[base + si][r], v, acc[r]);
    }
    const int chunk = tile * 2 + half;
    #pragma unroll
    for (int r = 0; r < R_N; r++)
        g_vpart[((chunk * H_N * R_N) + h * R_N + r) * FD + f] = acc[r];
}

// ---------------- K5b: reduce + BN over R + lrelu -> g_v --------------------
__global__ void k5b_bnv(const float* __restrict__ g1, const float* __restrict__ b1) {
    int i = blockIdx.x * blockDim.x + threadIdx.x;  // h*FD + f
    if (i >= H_N * FD) return;
    int h = i / FD, f = i % FD;
    float x[R_N];
    float m = 0.f;
    #pragma unroll
    for (int r = 0; r < R_N; r++) {
        float t = 0.f;
        for (int c = 0; c < NCH; c++)
            t += g_vpart[((c * H_N * R_N) + h * R_N + r) * FD + f];
        x[r] = t;
        m += t;
    }
    m *= (1.f / R_N);
    float var = 0.f;
    #pragma unroll
    for (int r = 0; r < R_N; r++) { float d = x[r] - m; var = fmaf(d, d, var); }
    var *= (1.f / R_N);
    float inv = rsqrtf(var + 1e-5f);
    float gg = g1[i], bb = b1[i];
    #pragma unroll
    for (int r = 0; r < R_N; r++)
        g_v[((h * R_N) + r) * FD + f] = lrelu((x[r] - m) * inv * gg + bb);
}

// ---------------- K6: u_pre = IntraNC (bf16 GEMM) + InterRC (fp32) -----------
// Pure HMMA GEMM: A = W[b][s] (ldmatrix.trans), B = y[b][f] (ldmatrix.trans).
// Fused BN column partial sums (replaces k7a).
// dyn smem: ash 2x32x136 bf16 (17408) | ysh same (17408) | attsh 128x17 f32
// (8704) | h1sh 16x128 f32 (8192) = 51712 bytes.
#define K6_SMEM 51712
__global__ __launch_bounds__(256, 2) void k6_u_mma() {
    extern __shared__ char sm6[];
    __nv_bfloat16 (*ash)[32][136] = (__nv_bfloat16(*)[32][136])sm6;
    __nv_bfloat16 (*ysh)[32][136] = (__nv_bfloat16(*)[32][136])(sm6 + 17408);
    float (*attsh)[17] = (float(*)[17])(sm6 + 34816);
    float (*h1sh)[128] = (float(*)[128])(sm6 + 43520);

    const int h = blockIdx.y, tile = blockIdx.x, s0 = tile * 128;
    const int tid = threadIdx.x, lane = tid & 31, w = tid >> 5;
    const int wm = w >> 1, wn = w & 1;     // 4 x 2 warp grid: 32m x 64n each
    const int g = lane >> 2, tg = lane & 3;

    for (int i = tid; i < 128 * R_N; i += 256) {
        int sl = i >> 4, r = i & 15;
        int s = s0 + sl;
        attsh[sl][r] = (s < S_N) ? g_att[((h * S_N) + s) * R_N + r] : 0.f;
    }
    for (int i = tid; i < R_N * FD; i += 256)
        h1sh[i >> 7][i & 127] = g_h1[h * R_N * FD + i];

    const int i0 = tid, i1 = tid + 256;
    const int ybl0 = i0 >> 4, yfo0 = (i0 & 15) * 8;
    const int ybl1 = i1 >> 4, yfo1 = (i1 & 15) * 8;

    float acc[2][8][4] = {};

    // prologue: stage chunk 0
    {
        const int b0 = 0;
        CP16(su(&ysh[0][ybl0][yfo0]), &g_h2sb[(((size_t)h * B_N) + b0 + ybl0) * FD + yfo0]);
        CP16(su(&ysh[0][ybl1][yfo1]), &g_h2sb[(((size_t)h * B_N) + b0 + ybl1) * FD + yfo1]);
        CP16(su(&ash[0][ybl0][yfo0]), &g_wb[((size_t)(b0 + ybl0)) * SP + s0 + yfo0]);
        CP16(su(&ash[0][ybl1][yfo1]), &g_wb[((size_t)(b0 + ybl1)) * SP + s0 + yfo1]);
        CPCOMMIT;
    }

    // A ldmatrix address components (W stored [k=b][m=s] -> x4.trans)
    const int krow = ((lane >> 4) << 3) + (lane & 7);
    const int mcol = wm * 32 + ((lane >> 3) & 1) * 8;

    for (int c = 0; c < 64; c++) {
        const int buf = c & 1;
        CPWAIT0;
        __syncthreads();
        if (c < 63) {
            const int b0 = (c + 1) * 32;
            const int nb = buf ^ 1;
            CP16(su(&ysh[nb][ybl0][yfo0]), &g_h2sb[(((size_t)h * B_N) + b0 + ybl0) * FD + yfo0]);
            CP16(su(&ysh[nb][ybl1][yfo1]), &g_h2sb[(((size_t)h * B_N) + b0 + ybl1) * FD + yfo1]);
            CP16(su(&ash[nb][ybl0][yfo0]), &g_wb[((size_t)(b0 + ybl0)) * SP + s0 + yfo0]);
            CP16(su(&ash[nb][ybl1][yfo1]), &g_wb[((size_t)(b0 + ybl1)) * SP + s0 + yfo1]);
            CPCOMMIT;
        }
        #pragma unroll
        for (int kh = 0; kh < 2; kh++) {
            const int kk = kh * 16;
            unsigned A[2][4];
            #pragma unroll
            for (int im = 0; im < 2; im++) {
                unsigned addr = su(&ash[buf][kk + krow][mcol + im * 16]);
                ldmx4t(A[im][0], A[im][1], A[im][2], A[im][3], addr);
            }
            unsigned Bf[8][2];
            #pragma unroll
            for (int q = 0; q < 4; q++) {
                const int col = wn * 64 + q * 16 + ((lane >> 4) << 3);
                const int row = kk + (lane & 15);
                unsigned addr = su(&ysh[buf][row][col]);
                unsigned r0, r1, r2, r3;
                ldmx4t(r0, r1, r2, r3, addr);
                Bf[q * 2][0] = r0; Bf[q * 2][1] = r1;
                Bf[q * 2 + 1][0] = r2; Bf[q * 2 + 1][1] = r3;
            }
            #pragma unroll
            for (int im = 0; im < 2; im++)
                #pragma unroll
                for (int in = 0; in < 8; in++)
                    mma_bf16(acc[im][in], A[im], Bf[in]);
        }
    }

    // epilogue: InterRC in fp32
    const int sb = wm * 32 + g;
    const int fb = wn * 64 + 2 * tg;
    #pragma unroll
    for (int r = 0; r < R_N; r++) {
        float a00 = attsh[sb][r],      a01 = attsh[sb + 8][r];
        float a10 = attsh[sb + 16][r], a11 = attsh[sb + 24][r];
        float hv0[8], hv1[8];
        #pragma unroll
        for (int in = 0; in < 8; in++) {
            hv0[in] = h1sh[r][fb + in * 8];
            hv1[in] = h1sh[r][fb + in * 8 + 1];
        }
        #pragma unroll
        for (int in = 0; in < 8; in++) {
            acc[0][in][0] = fmaf(a00, hv0[in], acc[0][in][0]);
            acc[0][in][1] = fmaf(a00, hv1[in], acc[0][in][1]);
            acc[0][in][2] = fmaf(a01, hv0[in], acc[0][in][2]);
            acc[0][in][3] = fmaf(a01, hv1[in], acc[0][in][3]);
            acc[1][in][0] = fmaf(a10, hv0[in], acc[1][in][0]);
            acc[1][in][1] = fmaf(a10, hv1[in], acc[1][in][1]);
            acc[1][in][2] = fmaf(a11, hv0[in], acc[1][in][2]);
            acc[1][in][3] = fmaf(a11, hv1[in], acc[1][in][3]);
        }
    }
    // store u
    #pragma unroll
    for (int im = 0; im < 2; im++)
        #pragma unroll
        for (int hf = 0; hf < 2; hf++) {
            int s = s0 + wm * 32 + im * 16 + g + hf * 8;
            if (s < S_N) {
                float* up = &g_u[((size_t)h * S_N + s) * FD + fb];
                #pragma unroll
                for (int in = 0; in < 8; in++) {
                    float2 o = make_float2(acc[im][in][hf * 2], acc[im][in][hf * 2 + 1]);
                    *(float2*)(up + in * 8) = o;
                }
            }
        }
    // fused BN column partials (rows s>=S_N contribute exact zeros)
    __syncthreads();
    float* rs = (float*)sm6;          // reuse ash region (4KB)
    float* rq = rs + 512;
    #pragma unroll
    for (int in = 0; in < 8; in++)
        #pragma unroll
        for (int half = 0; half < 2; half++) {
            float a0 = acc[0][in][half],     a1 = acc[0][in][2 + half];
            float a2 = acc[1][in][half],     a3 = acc[1][in][2 + half];
            float sm_ = a0 + a1 + a2 + a3;
            float sq_ = a0 * a0 + a1 * a1 + a2 * a2 + a3 * a3;
            #pragma unroll
            for (int o = 4; o <= 16; o <<= 1) {
                sm_ += __shfl_xor_sync(0xffffffffu, sm_, o);
                sq_ += __shfl_xor_sync(0xffffffffu, sq_, o);
            }
            if (lane < 4) {
                int f = wn * 64 + in * 8 + 2 * lane + half;
                rs[wm * 128 + f] = sm_;
                rq[wm * 128 + f] = sq_;
            }
        }
    __syncthreads();
    if (tid < 128) {
        float s4 = rs[tid] + rs[128 + tid] + rs[256 + tid] + rs[384 + tid];
        float q4 = rq[tid] + rq[128 + tid] + rq[256 + tid] + rq[384 + tid];
        g_upsum[tile * H_N * FD + h * FD + tid] = s4;
        g_upsq [tile * H_N * FD + h * FD + tid] = q4;
    }
}

// ---------------- K7b: BN affine coefficients for u -------------------------
__global__ void k7b_bnu(const float* __restrict__ g2, const float* __restrict__ b2) {
    int i = blockIdx.x * blockDim.x + threadIdx.x;
    if (i >= H_N * FD) return;
    float sm = 0.f, sq = 0.f;
    for (int c = 0; c < 79; c++) {
        sm += g_upsum[c * H_N * FD + i];
        sq += g_upsq [c * H_N * FD + i];
    }
    float mean = sm / (float)S_N;
    float var = sq / (float)S_N - mean * mean;
    float al = g2[i] * rsqrtf(var + 1e-5f);
    g_alpha[i] = al;
    g_beta[i]  = b2[i] - mean * al;
}

// ---------------- K8: epilogue (warp per s) ----------------------------------
__global__ void k8_out(const int* __restrict__ inter, const float* __restrict__ outW,
                       float* __restrict__ out) {
    int s = blockIdx.x * 8 + (threadIdx.x >> 5);
    int lane = threadIdx.x & 31;
    if (s >= S_N) return;
    float un[H_N][4];
    #pragma unroll
    for (int h = 0; h < H_N; h++)
        #pragma unroll
        for (int i = 0; i < 4; i++) {
            int f = lane + 32 * i;
            float x = g_u[((size_t)h * S_N + s) * FD + f];
            un[h][i] = lrelu(fmaf(x, g_alpha[h * FD + f], g_beta[h * FD + f]));
        }
    float hf = 0.f;  // lane < 16 holds hfin[lane]
    #pragma unroll
    for (int h = 0; h < H_N; h++)
        for (int r = 0; r < R_N; r++) {
            float d = 0.f;
            #pragma unroll
            for (int i = 0; i < 4; i++) {
                int f = lane + 32 * i;
                d = fmaf(un[h][i], g_v[((h * R_N) + r) * FD + f], d);
            }
            #pragma unroll
            for (int o = 16; o > 0; o >>= 1) d += __shfl_xor_sync(0xffffffffu, d, o);
            float ho = elu(d);
            if (lane < C_N) hf = fmaf(ho, outW[(h * R_N + r) * C_N + lane], hf);
        }
    int adj = (lane < R_N) ? inter[s * R_N + lane] : 0;
    unsigned m = __ballot_sync(0xffffffffu, (lane < R_N) && adj > 0);
    int deg = __popc(m);
    float att = (deg > 0) ? (adj > 0 ? 1.f / (float)deg : 0.f) : (1.f / (float)R_N);
    float t = att * hf;
    t = elu(t);
    t = elu(t);
    float z = (lane < C_N) ? t : -3.4e38f;
    float mx = z;
    #pragma unroll
    for (int o = 8; o > 0; o >>= 1) mx = fmaxf(mx, __shfl_xor_sync(0xffffffffu, mx, o));
    float ex = (lane < C_N) ? expf(z - mx) : 0.f;
    float sm = ex;
    #pragma unroll
    for (int o = 8; o > 0; o >>= 1) sm += __shfl_xor_sync(0xffffffffu, sm, o);
    if (lane < C_N) out[s * C_N + lane] = (z - mx) - logf(sm);
}

// ---------------- launch -----------------------------------------------------
extern "C" void kernel_launch(void* const* d_in, const int* in_sizes, int n_in,
                              void* d_out, int out_size) {
    const int*   inter = (const int*)d_in[0];
    const int*   city  = (const int*)d_in[1];
    const int*   prov  = (const int*)d_in[2];
    const int*   src   = (const int*)d_in[3];
    const float* Sfeat = (const float*)d_in[4];
    const float* Rfeat = (const float*)d_in[5];
    const float* W1    = (const float*)d_in[6];
    const float* W2    = (const float*)d_in[7];
    const float* a     = (const float*)d_in[8];
    // d_in[9] (a3), d_in[10] (a4), d_in[16] (outA): provably dead inputs
    const float* bn1g  = (const float*)d_in[11];
    const float* bn1b  = (const float*)d_in[12];
    const float* bn2g  = (const float*)d_in[13];
    const float* bn2b  = (const float*)d_in[14];
    const float* outW  = (const float*)d_in[15];
    float* out = (float*)d_out;

    cudaFuncSetAttribute(k6_u_mma, cudaFuncAttributeMaxDynamicSharedMemorySize, K6_SMEM);

    k1_h1<<<H_N * R_N, 128>>>(Rfeat, W1, a);
    k2_h2<<<dim3((S_N + 63) / 64, H_N), 256>>>(Sfeat, W2);
    k3_bits<<<B_N, 256>>>(city, prov, src);
    k3w_wb<<<B_N, 256>>>();
    k3b_gather<<<dim3(B_N, H_N), 128>>>(src);
    k45_attv<<<dim3(79, H_N), 256>>>(inter, a);
    k5b_bnv<<<(H_N * FD + 127) / 128, 128>>>(bn1g, bn1b);
    k6_u_mma<<<dim3(79, H_N), 256, K6_SMEM>>>();
    k7b_bnu<<<(H_N * FD + 127) / 128, 128>>>(bn2g, bn2b);
    k8_out<<<(S_N + 7) / 8, 256>>>(inter, outW, out);
}

// round 5
// speedup vs baseline: 1.0044x; 1.0044x over previous
#include <cuda_runtime.h>
#include <cuda_bf16.h>
#include <math.h>

#define S_N 10000
#define R_N 16
#define FD 128
#define H_N 4
#define B_N 2048
#define C_N 16
#define NEG (-9e15f)
#define SW 313        // ceil(S/32) words per bitmask row
#define SP 10112      // 79*128, padded S for W matrix
#define NCH 158       // vpart chunks (79 tiles x 2 halves)

// ---------------- scratch (device globals; no allocation allowed) ----------
__device__ float g_h1[H_N * R_N * FD];             // [H][R][F]
__device__ float g_h1a[H_N * R_N];                 // h1 . a[:F]
__device__ float g_h2[(size_t)H_N * S_N * FD];     // [H][S][F]
__device__ __nv_bfloat16 g_h2sb[H_N * B_N * FD];   // gathered h2[src], bf16
__device__ unsigned g_cbits[B_N * SW];
__device__ unsigned g_pbits[B_N * SW];
__device__ float2 g_inv2[B_N];                     // (1/degc, 1/degp)
__device__ __nv_bfloat16 g_wb[(size_t)B_N * SP];   // W[b][s] bf16 (zero-padded)
__device__ float g_att[H_N * S_N * R_N];           // inter attention
__device__ float g_vpart[NCH * H_N * R_N * FD];    // partial sums for v
__device__ float g_v[H_N * R_N * FD];              // post-BN, lrelu'd v
__device__ float g_u[(size_t)H_N * S_N * FD];      // pre-BN u
__device__ float g_upsum[79 * H_N * FD];
__device__ float g_upsq[79 * H_N * FD];
__device__ float g_alpha[H_N * FD];
__device__ float g_beta[H_N * FD];

__device__ __forceinline__ float lrelu(float x) { return x > 0.f ? x : 0.2f * x; }
__device__ __forceinline__ float elu(float x)   { return x > 0.f ? x : expm1f(x); }
__device__ __forceinline__ unsigned su(const void* p) {
    return (unsigned)__cvta_generic_to_shared(p);
}
__device__ __forceinline__ void mma_bf16(float c[4], const unsigned a[4], const unsigned b[2]) {
    asm volatile(
        "mma.sync.aligned.m16n8k16.row.col.f32.bf16.bf16.f32 "
        "{%0,%1,%2,%3},{%4,%5,%6,%7},{%8,%9},{%0,%1,%2,%3};"
        : "+f"(c[0]), "+f"(c[1]), "+f"(c[2]), "+f"(c[3])
        : "r"(a[0]), "r"(a[1]), "r"(a[2]), "r"(a[3]), "r"(b[0]), "r"(b[1]));
}
__device__ __forceinline__ void ldmx4t(unsigned& r0, unsigned& r1, unsigned& r2, unsigned& r3,
                                       unsigned addr) {
    asm volatile("ldmatrix.sync.aligned.m8n8.x4.trans.shared.b16 {%0,%1,%2,%3},[%4];"
                 : "=r"(r0), "=r"(r1), "=r"(r2), "=r"(r3) : "r"(addr));
}
#define CP16(d, s) asm volatile("cp.async.cg.shared.global [%0],[%1],16;" ::"r"(d), "l"(s))
#define CPCOMMIT   asm volatile("cp.async.commit_group;")
#define CPWAIT0    asm volatile("cp.async.wait_group 0;")

// ---------------- K1: h1 = Rfeat @ W1[h], h1a = h1 . a[:F] ------------------
__global__ void k1_h1(const float* __restrict__ Rfeat, const float* __restrict__ W1,
                      const float* __restrict__ a) {
    int h = blockIdx.x / R_N, r = blockIdx.x % R_N, f = threadIdx.x;
    const float* w  = W1 + (size_t)h * FD * FD;
    const float* rf = Rfeat + r * FD;
    float acc = 0.f;
    #pragma unroll 8
    for (int k = 0; k < FD; k++) acc = fmaf(rf[k], w[k * FD + f], acc);
    g_h1[(h * R_N + r) * FD + f] = acc;
    __shared__ float sh[128];
    sh[f] = acc * a[h * 2 * FD + f];
    __syncthreads();
    for (int st = 64; st > 0; st >>= 1) {
        if (f < st) sh[f] += sh[f + st];
        __syncthreads();
    }
    if (f == 0) g_h1a[h * R_N + r] = sh[0];
}

// ---------------- K2: h2 = Sfeat @ W2[h]  (broadcast-smem register blocked) -
__global__ __launch_bounds__(256) void k2_h2(const float* __restrict__ Sfeat,
                                             const float* __restrict__ W2) {
    const int h = blockIdx.y;
    const int s0 = blockIdx.x * 64;
    const int tid = threadIdx.x;
    const int tx = tid & 31;        // f = 4*tx
    const int ty = tid >> 5;        // s group of 8
    __shared__ float sf[FD][68];    // [k][s], stride 68 (16B aligned rows)
    for (int i = tid; i < 64 * FD; i += 256) {
        int sl = i >> 7, k = i & 127;
        int s = s0 + sl;
        sf[k][sl] = (s < S_N) ? Sfeat[(size_t)s * FD + k] : 0.f;
    }
    __syncthreads();
    float acc[8][4];
    #pragma unroll
    for (int i = 0; i < 8; i++)
        #pragma unroll
        for (int j = 0; j < 4; j++) acc[i][j] = 0.f;
    const float4* w4 = (const float4*)(W2 + (size_t)h * FD * FD);
    #pragma unroll 4
    for (int k = 0; k < FD; k++) {
        float4 wv = w4[k * 32 + tx];
        float4 sa = *(const float4*)&sf[k][ty * 8];
        float4 sb = *(const float4*)&sf[k][ty * 8 + 4];
        float sv[8] = {sa.x, sa.y, sa.z, sa.w, sb.x, sb.y, sb.z, sb.w};
        #pragma unroll
        for (int i = 0; i < 8; i++) {
            acc[i][0] = fmaf(sv[i], wv.x, acc[i][0]);
            acc[i][1] = fmaf(sv[i], wv.y, acc[i][1]);
            acc[i][2] = fmaf(sv[i], wv.z, acc[i][2]);
            acc[i][3] = fmaf(sv[i], wv.w, acc[i][3]);
        }
    }
    #pragma unroll
    for (int i = 0; i < 8; i++) {
        int s = s0 + ty * 8 + i;
        if (s < S_N) {
            float4 o = make_float4(acc[i][0], acc[i][1], acc[i][2], acc[i][3]);
            *(float4*)&g_h2[((size_t)h * S_N + s) * FD + tx * 4] = o;
        }
    }
}

// ---------------- K3: bitpack gathered adjacency rows + degrees -------------
__global__ void k3_bits(const int* __restrict__ city, const int* __restrict__ prov,
                        const int* __restrict__ src) {
    int b = blockIdx.x;
    int n = src[b];
    const int* crow = city + (size_t)n * S_N;
    const int* prow = prov + (size_t)n * S_N;
    int lane = threadIdx.x & 31, wid = threadIdx.x >> 5;  // 8 warps
    int degc = 0, degp = 0;
    for (int w = wid; w < SW; w += 8) {
        int s = w * 32 + lane;
        bool inb = s < S_N;
        int cv = inb ? crow[s] : 0;
        int pv = inb ? prow[s] : 0;
        unsigned cm = __ballot_sync(0xffffffffu, cv > 0);
        unsigned pm = __ballot_sync(0xffffffffu, pv > 0);
        if (lane == 0) {
            g_cbits[b * SW + w] = cm;
            g_pbits[b * SW + w] = pm;
            degc += __popc(cm);
            degp += __popc(pm);
        }
    }
    __shared__ int sdc[8], sdp[8];
    if (lane == 0) { sdc[wid] = degc; sdp[wid] = degp; }
    __syncthreads();
    if (threadIdx.x == 0) {
        int dc = 0, dp = 0;
        for (int i = 0; i < 8; i++) { dc += sdc[i]; dp += sdp[i]; }
        g_inv2[b] = make_float2(dc > 0 ? 1.f / (float)dc : 0.f,
                                dp > 0 ? 1.f / (float)dp : 0.f);
    }
}

// ---------------- K3w: materialize W[b][s] in bf16 ---------------------------
__global__ void k3w_wb() {
    int b = blockIdx.x;
    float2 iv = g_inv2[b];
    const unsigned* cb = g_cbits + (size_t)b * SW;
    const unsigned* pb = g_pbits + (size_t)b * SW;
    __nv_bfloat16* wrow = g_wb + (size_t)b * SP;
    for (int s = threadIdx.x; s < SP; s += blockDim.x) {
        float v = 0.f;
        if (s < S_N) {
            unsigned cw = cb[s >> 5], pw = pb[s >> 5];
            int bit = s & 31;
            v = ((cw >> bit) & 1u) ? iv.x : 0.f;
            if ((pw >> bit) & 1u) v += iv.y;
        }
        wrow[s] = __float2bfloat16(v);
    }
}

// ---------------- K3b: gather h2s = h2[src] (bf16) --------------------------
__global__ void k3b_gather(const int* __restrict__ src) {
    int h = blockIdx.y, b = blockIdx.x, f = threadIdx.x;
    int n = src[b];
    g_h2sb[((h * B_N) + b) * FD + f] =
        __float2bfloat16(g_h2[((size_t)h * S_N + n) * FD + f]);
}

// ---------------- K45: inter attention + v partials (fused) ------------------
__global__ __launch_bounds__(256) void k45_attv(const int* __restrict__ inter,
                                                const float* __restrict__ a) {
    const int h = blockIdx.y, tile = blockIdx.x, s0 = tile * 128;
    const int tid = threadIdx.x, lane = tid & 31, w = tid >> 5;
    __shared__ float attS[128][17];
    const float* a2 = a + h * 2 * FD + FD;
    float a2v[4];
    #pragma unroll
    for (int i = 0; i < 4; i++) a2v[i] = a2[lane + 32 * i];
    // phase 1: attention rows
    for (int it = 0; it < 16; it++) {
        int sl = w * 16 + it;
        int s = s0 + sl;
        if (s < S_N) {
            const float* row = &g_h2[((size_t)h * S_N + s) * FD];
            float d = 0.f;
            #pragma unroll
            for (int i = 0; i < 4; i++) d = fmaf(row[lane + 32 * i], a2v[i], d);
            #pragma unroll
            for (int o = 16; o > 0; o >>= 1) d += __shfl_xor_sync(0xffffffffu, d, o);
            float z = NEG;
            if (lane < R_N && inter[s * R_N + lane] > 0)
                z = lrelu(d + g_h1a[h * R_N + lane]);
            float mx = z;
            #pragma unroll
            for (int o = 8; o > 0; o >>= 1) mx = fmaxf(mx, __shfl_xor_sync(0xffffffffu, mx, o));
            float ex = (lane < R_N) ? expf(z - mx) : 0.f;
            float sm = ex;
            #pragma unroll
            for (int o = 8; o > 0; o >>= 1) sm += __shfl_xor_sync(0xffffffffu, sm, o);
            if (lane < R_N) {
                float av = ex / sm;
                attS[sl][lane] = av;
                g_att[((h * S_N) + s) * R_N + lane] = av;
            }
        } else if (lane < R_N) {
            attS[sl][lane] = 0.f;
        }
    }
    __syncthreads();
    // phase 2: vpart for this half-chunk
    const int f = tid & 127, half = tid >> 7;
    float acc[R_N];
    #pragma unroll
    for (int r = 0; r < R_N; r++) acc[r] = 0.f;
    const int base = half * 64;
    for (int si = 0; si < 64; si++) {
        int s = s0 + base + si;
        if (s >= S_N) break;
        float v = g_h2[((size_t)h * S_N + s) * FD + f];
        #pragma unroll
        for (int r = 0; r < R_N; r++) acc[r] = fmaf(attS[base + si][r], v, acc[r]);
    }
    const int chunk = tile * 2 + half;
    #pragma unroll
    for (int r = 0; r < R_N; r++)
        g_vpart[((chunk * H_N * R_N) + h * R_N + r) * FD + f] = acc[r];
}

// ---------------- K5b: reduce + BN over R + lrelu -> g_v --------------------
__global__ void k5b_bnv(const float* __restrict__ g1, const float* __restrict__ b1) {
    int i = blockIdx.x * blockDim.x + threadIdx.x;  // h*FD + f
    if (i >= H_N * FD) return;
    int h = i / FD, f = i % FD;
    float x[R_N];
    float m = 0.f;
    #pragma unroll
    for (int r = 0; r < R_N; r++) {
        float t = 0.f;
        for (int c = 0; c < NCH; c++)
            t += g_vpart[((c * H_N * R_N) + h * R_N + r) * FD + f];
        x[r] = t;
        m += t;
    }
    m *= (1.f / R_N);
    float var = 0.f;
    #pragma unroll
    for (int r = 0; r < R_N; r++) { float d = x[r] - m; var = fmaf(d, d, var); }
    var *= (1.f / R_N);
    float inv = rsqrtf(var + 1e-5f);
    float gg = g1[i], bb = b1[i];
    #pragma unroll
    for (int r = 0; r < R_N; r++)
        g_v[((h * R_N) + r) * FD + f] = lrelu((x[r] - m) * inv * gg + bb);
}

// ---------------- K6: u_pre = IntraNC (bf16 GEMM) + InterRC (fp32) -----------
// Pure HMMA GEMM: A = W[b][s] (ldmatrix.trans), B = y[b][f] (ldmatrix.trans).
// Fused BN column partial sums (replaces k7a).
// dyn smem: ash 2x32x136 bf16 (17408) | ysh same (17408) | attsh 128x17 f32
// (8704) | h1sh 16x128 f32 (8192) = 51712 bytes.
#define K6_SMEM 51712
__global__ __launch_bounds__(256, 2) void k6_u_mma() {
    extern __shared__ char sm6[];
    __nv_bfloat16 (*ash)[32][136] = (__nv_bfloat16(*)[32][136])sm6;
    __nv_bfloat16 (*ysh)[32][136] = (__nv_bfloat16(*)[32][136])(sm6 + 17408);
    float (*attsh)[17] = (float(*)[17])(sm6 + 34816);
    float (*h1sh)[128] = (float(*)[128])(sm6 + 43520);

    const int h = blockIdx.y, tile = blockIdx.x, s0 = tile * 128;
    const int tid = threadIdx.x, lane = tid & 31, w = tid >> 5;
    const int wm = w >> 1, wn = w & 1;     // 4 x 2 warp grid: 32m x 64n each
    const int g = lane >> 2, tg = lane & 3;

    for (int i = tid; i < 128 * R_N; i += 256) {
        int sl = i >> 4, r = i & 15;
        int s = s0 + sl;
        attsh[sl][r] = (s < S_N) ? g_att[((h * S_N) + s) * R_N + r] : 0.f;
    }
    for (int i = tid; i < R_N * FD; i += 256)
        h1sh[i >> 7][i & 127] = g_h1[h * R_N * FD + i];

    const int i0 = tid, i1 = tid + 256;
    const int ybl0 = i0 >> 4, yfo0 = (i0 & 15) * 8;
    const int ybl1 = i1 >> 4, yfo1 = (i1 & 15) * 8;

    float acc[2][8][4] = {};

    // prologue: stage chunk 0
    {
        const int b0 = 0;
        CP16(su(&ysh[0][ybl0][yfo0]), &g_h2sb[(((size_t)h * B_N) + b0 + ybl0) * FD + yfo0]);
        CP16(su(&ysh[0][ybl1][yfo1]), &g_h2sb[(((size_t)h * B_N) + b0 + ybl1) * FD + yfo1]);
        CP16(su(&ash[0][ybl0][yfo0]), &g_wb[((size_t)(b0 + ybl0)) * SP + s0 + yfo0]);
        CP16(su(&ash[0][ybl1][yfo1]), &g_wb[((size_t)(b0 + ybl1)) * SP + s0 + yfo1]);
        CPCOMMIT;
    }

    // A ldmatrix address components (W stored [k=b][m=s] -> x4.trans)
    const int krow = ((lane >> 4) << 3) + (lane & 7);
    const int mcol = wm * 32 + ((lane >> 3) & 1) * 8;

    for (int c = 0; c < 64; c++) {
        const int buf = c & 1;
        CPWAIT0;
        __syncthreads();
        if (c < 63) {
            const int b0 = (c + 1) * 32;
            const int nb = buf ^ 1;
            CP16(su(&ysh[nb][ybl0][yfo0]), &g_h2sb[(((size_t)h * B_N) + b0 + ybl0) * FD + yfo0]);
            CP16(su(&ysh[nb][ybl1][yfo1]), &g_h2sb[(((size_t)h * B_N) + b0 + ybl1) * FD + yfo1]);
            CP16(su(&ash[nb][ybl0][yfo0]), &g_wb[((size_t)(b0 + ybl0)) * SP + s0 + yfo0]);
            CP16(su(&ash[nb][ybl1][yfo1]), &g_wb[((size_t)(b0 + ybl1)) * SP + s0 + yfo1]);
            CPCOMMIT;
        }
        #pragma unroll
        for (int kh = 0; kh < 2; kh++) {
            const int kk = kh * 16;
            unsigned A[2][4];
            #pragma unroll
            for (int im = 0; im < 2; im++) {
                unsigned addr = su(&ash[buf][kk + krow][mcol + im * 16]);
                ldmx4t(A[im][0], A[im][1], A[im][2], A[im][3], addr);
            }
            unsigned Bf[8][2];
            #pragma unroll
            for (int q = 0; q < 4; q++) {
                const int col = wn * 64 + q * 16 + ((lane >> 4) << 3);
                const int row = kk + (lane & 15);
                unsigned addr = su(&ysh[buf][row][col]);
                unsigned r0, r1, r2, r3;
                ldmx4t(r0, r1, r2, r3, addr);
                Bf[q * 2][0] = r0; Bf[q * 2][1] = r1;
                Bf[q * 2 + 1][0] = r2; Bf[q * 2 + 1][1] = r3;
            }
            #pragma unroll
            for (int im = 0; im < 2; im++)
                #pragma unroll
                for (int in = 0; in < 8; in++)
                    mma_bf16(acc[im][in], A[im], Bf[in]);
        }
    }

    // epilogue: InterRC in fp32
    const int sb = wm * 32 + g;
    const int fb = wn * 64 + 2 * tg;
    #pragma unroll
    for (int r = 0; r < R_N; r++) {
        float a00 = attsh[sb][r],      a01 = attsh[sb + 8][r];
        float a10 = attsh[sb + 16][r], a11 = attsh[sb + 24][r];
        float hv0[8], hv1[8];
        #pragma unroll
        for (int in = 0; in < 8; in++) {
            hv0[in] = h1sh[r][fb + in * 8];
            hv1[in] = h1sh[r][fb + in * 8 + 1];
        }
        #pragma unroll
        for (int in = 0; in < 8; in++) {
            acc[0][in][0] = fmaf(a00, hv0[in], acc[0][in][0]);
            acc[0][in][1] = fmaf(a00, hv1[in], acc[0][in][1]);
            acc[0][in][2] = fmaf(a01, hv0[in], acc[0][in][2]);
            acc[0][in][3] = fmaf(a01, hv1[in], acc[0][in][3]);
            acc[1][in][0] = fmaf(a10, hv0[in], acc[1][in][0]);
            acc[1][in][1] = fmaf(a10, hv1[in], acc[1][in][1]);
            acc[1][in][2] = fmaf(a11, hv0[in], acc[1][in][2]);
            acc[1][in][3] = fmaf(a11, hv1[in], acc[1][in][3]);
        }
    }
    // store u
    #pragma unroll
    for (int im = 0; im < 2; im++)
        #pragma unroll
        for (int hf = 0; hf < 2; hf++) {
            int s = s0 + wm * 32 + im * 16 + g + hf * 8;
            if (s < S_N) {
                float* up = &g_u[((size_t)h * S_N + s) * FD + fb];
                #pragma unroll
                for (int in = 0; in < 8; in++) {
                    float2 o = make_float2(acc[im][in][hf * 2], acc[im][in][hf * 2 + 1]);
                    *(float2*)(up + in * 8) = o;
                }
            }
        }
    // fused BN column partials (rows s>=S_N contribute exact zeros)
    __syncthreads();
    float* rs = (float*)sm6;          // reuse ash region (4KB)
    float* rq = rs + 512;
    #pragma unroll
    for (int in = 0; in < 8; in++)
        #pragma unroll
        for (int half = 0; half < 2; half++) {
            float a0 = acc[0][in][half],     a1 = acc[0][in][2 + half];
            float a2 = acc[1][in][half],     a3 = acc[1][in][2 + half];
            float sm_ = a0 + a1 + a2 + a3;
            float sq_ = a0 * a0 + a1 * a1 + a2 * a2 + a3 * a3;
            #pragma unroll
            for (int o = 4; o <= 16; o <<= 1) {
                sm_ += __shfl_xor_sync(0xffffffffu, sm_, o);
                sq_ += __shfl_xor_sync(0xffffffffu, sq_, o);
            }
            if (lane < 4) {
                int f = wn * 64 + in * 8 + 2 * lane + half;
                rs[wm * 128 + f] = sm_;
                rq[wm * 128 + f] = sq_;
            }
        }
    __syncthreads();
    if (tid < 128) {
        float s4 = rs[tid] + rs[128 + tid] + rs[256 + tid] + rs[384 + tid];
        float q4 = rq[tid] + rq[128 + tid] + rq[256 + tid] + rq[384 + tid];
        g_upsum[tile * H_N * FD + h * FD + tid] = s4;
        g_upsq [tile * H_N * FD + h * FD + tid] = q4;
    }
}

// ---------------- K7b: BN affine coefficients for u -------------------------
__global__ void k7b_bnu(const float* __restrict__ g2, const float* __restrict__ b2) {
    int i = blockIdx.x * blockDim.x + threadIdx.x;
    if (i >= H_N * FD) return;
    float sm = 0.f, sq = 0.f;
    for (int c = 0; c < 79; c++) {
        sm += g_upsum[c * H_N * FD + i];
        sq += g_upsq [c * H_N * FD + i];
    }
    float mean = sm / (float)S_N;
    float var = sq / (float)S_N - mean * mean;
    float al = g2[i] * rsqrtf(var + 1e-5f);
    g_alpha[i] = al;
    g_beta[i]  = b2[i] - mean * al;
}

// ---------------- K8: epilogue (warp per s) ----------------------------------
__global__ void k8_out(const int* __restrict__ inter, const float* __restrict__ outW,
                       float* __restrict__ out) {
    int s = blockIdx.x * 8 + (threadIdx.x >> 5);
    int lane = threadIdx.x & 31;
    if (s >= S_N) return;
    float un[H_N][4];
    #pragma unroll
    for (int h = 0; h < H_N; h++)
        #pragma unroll
        for (int i = 0; i < 4; i++) {
            int f = lane + 32 * i;
            float x = g_u[((size_t)h * S_N + s) * FD + f];
            un[h][i] = lrelu(fmaf(x, g_alpha[h * FD + f], g_beta[h * FD + f]));
        }
    float hf = 0.f;  // lane < 16 holds hfin[lane]
    #pragma unroll
    for (int h = 0; h < H_N; h++)
        for (int r = 0; r < R_N; r++) {
            float d = 0.f;
            #pragma unroll
            for (int i = 0; i < 4; i++) {
                int f = lane + 32 * i;
                d = fmaf(un[h][i], g_v[((h * R_N) + r) * FD + f], d);
            }
            #pragma unroll
            for (int o = 16; o > 0; o >>= 1) d += __shfl_xor_sync(0xffffffffu, d, o);
            float ho = elu(d);
            if (lane < C_N) hf = fmaf(ho, outW[(h * R_N + r) * C_N + lane], hf);
        }
    int adj = (lane < R_N) ? inter[s * R_N + lane] : 0;
    unsigned m = __ballot_sync(0xffffffffu, (lane < R_N) && adj > 0);
    int deg = __popc(m);
    float att = (deg > 0) ? (adj > 0 ? 1.f / (float)deg : 0.f) : (1.f / (float)R_N);
    float t = att * hf;
    t = elu(t);
    t = elu(t);
    float z = (lane < C_N) ? t : -3.4e38f;
    float mx = z;
    #pragma unroll
    for (int o = 8; o > 0; o >>= 1) mx = fmaxf(mx, __shfl_xor_sync(0xffffffffu, mx, o));
    float ex = (lane < C_N) ? expf(z - mx) : 0.f;
    float sm = ex;
    #pragma unroll
    for (int o = 8; o > 0; o >>= 1) sm += __shfl_xor_sync(0xffffffffu, sm, o);
    if (lane < C_N) out[s * C_N + lane] = (z - mx) - logf(sm);
}

// ---------------- launch -----------------------------------------------------
extern "C" void kernel_launch(void* const* d_in, const int* in_sizes, int n_in,
                              void* d_out, int out_size) {
    const int*   inter = (const int*)d_in[0];
    const int*   city  = (const int*)d_in[1];
    const int*   prov  = (const int*)d_in[2];
    const int*   src   = (const int*)d_in[3];
    const float* Sfeat = (const float*)d_in[4];
    const float* Rfeat = (const float*)d_in[5];
    const float* W1    = (const float*)d_in[6];
    const float* W2    = (const float*)d_in[7];
    const float* a     = (const float*)d_in[8];
    // d_in[9] (a3), d_in[10] (a4), d_in[16] (outA): provably dead inputs
    const float* bn1g  = (const float*)d_in[11];
    const float* bn1b  = (const float*)d_in[12];
    const float* bn2g  = (const float*)d_in[13];
    const float* bn2b  = (const float*)d_in[14];
    const float* outW  = (const float*)d_in[15];
    float* out = (float*)d_out;

    cudaFuncSetAttribute(k6_u_mma, cudaFuncAttributeMaxDynamicSharedMemorySize, K6_SMEM);

    k1_h1<<<H_N * R_N, 128>>>(Rfeat, W1, a);
    k2_h2<<<dim3((S_N + 63) / 64, H_N), 256>>>(Sfeat, W2);
    k3_bits<<<B_N, 256>>>(city, prov, src);
    k3w_wb<<<B_N, 256>>>();
    k3b_gather<<<dim3(B_N, H_N), 128>>>(src);
    k45_attv<<<dim3(79, H_N), 256>>>(inter, a);
    k5b_bnv<<<(H_N * FD + 127) / 128, 128>>>(bn1g, bn1b);
    k6_u_mma<<<dim3(79, H_N), 256, K6_SMEM>>>();
    k7b_bnu<<<(H_N * FD + 127) / 128, 128>>>(bn2g, bn2b);
    k8_out<<<(S_N + 7) / 8, 256>>>(inter, outW, out);
}

// round 8
// speedup vs baseline: 1.0768x; 1.0721x over previous
#include <cuda_runtime.h>
#include <cuda_bf16.h>
#include <cuda_fp8.h>
#include <math.h>
#include <stdint.h>

#define S_N 10000
#define R_N 16
#define FD 128
#define H_N 4
#define B_N 2048
#define C_N 16
#define NEG (-9e15f)
#define SW 313
#define SP 10112
#define NCH 158

__device__ float g_h1[H_N * R_N * FD];
__device__ float g_h1a[H_N * R_N];
__device__ float g_h2[(size_t)H_N * S_N * FD];
__device__ unsigned g_cbits[B_N * SW];
__device__ unsigned g_pbits[B_N * SW];
__device__ float2 g_inv2[B_N];
__device__ unsigned char g_wbt8[(size_t)SP * B_N];      // (4096*W)^T [s][b] e4m3
__device__ unsigned char g_ybt8[(size_t)H_N * FD * B_N]; // (16*y)^T [h][f][b] e4m3
__device__ float g_att[H_N * S_N * R_N];
__device__ float g_vpart[NCH * H_N * R_N * FD];
__device__ float g_v[H_N * R_N * FD];
__device__ float g_u[(size_t)H_N * S_N * FD];
__device__ float g_upsum[79 * H_N * FD];
__device__ float g_upsq[79 * H_N * FD];
__device__ float g_alpha[H_N * FD];
__device__ float g_beta[H_N * FD];

__device__ __forceinline__ float lrelu(float x) { return x > 0.f ? x : 0.2f * x; }
__device__ __forceinline__ float elu(float x)   { return x > 0.f ? x : expm1f(x); }
__device__ __forceinline__ unsigned su(const void* p) {
    return (unsigned)__cvta_generic_to_shared(p);
}
__device__ __forceinline__ void ldmx4(unsigned& r0, unsigned& r1, unsigned& r2,
                                      unsigned& r3, unsigned addr) {
    asm volatile("ldmatrix.sync.aligned.m8n8.x4.shared.b16 {%0,%1,%2,%3},[%4];"
                 : "=r"(r0), "=r"(r1), "=r"(r2), "=r"(r3) : "r"(addr));
}
__device__ __forceinline__ void mma_f8(float c[4], const unsigned a[4], const unsigned b[2]) {
    asm volatile(
        "mma.sync.aligned.m16n8k32.row.col.f32.e4m3.e4m3.f32 "
        "{%0,%1,%2,%3},{%4,%5,%6,%7},{%8,%9},{%0,%1,%2,%3};"
        : "+f"(c[0]), "+f"(c[1]), "+f"(c[2]), "+f"(c[3])
        : "r"(a[0]), "r"(a[1]), "r"(a[2]), "r"(a[3]), "r"(b[0]), "r"(b[1]));
}
// cvt d, x, y -> x in HIGH byte, y in LOW byte
__device__ __forceinline__ unsigned short f8pack(float lo, float hi) {
    unsigned short p;
    asm("cvt.rn.satfinite.e4m3x2.f32 %0, %1, %2;" : "=h"(p) : "f"(hi), "f"(lo));
    return p;
}
#define CP16(d, s) asm volatile("cp.async.cg.shared.global [%0],[%1],16;" ::"r"(d), "l"(s))
#define CPCOMMIT   asm volatile("cp.async.commit_group;")
#define CPWAIT0    asm volatile("cp.async.wait_group 0;")

// ---- K3: bitpack adjacency + degrees ----
__global__ void k3_bits(const int* __restrict__ city, const int* __restrict__ prov,
                        const int* __restrict__ src) {
    int b = blockIdx.x;
    int n = src[b];
    const int* crow = city + (size_t)n * S_N;
    const int* prow = prov + (size_t)n * S_N;
    int lane = threadIdx.x & 31, wid = threadIdx.x >> 5;
    int degc = 0, degp = 0;
    for (int w = wid; w < SW; w += 8) {
        int s = w * 32 + lane;
        bool inb = s < S_N;
        int cv = inb ? crow[s] : 0;
        int pv = inb ? prow[s] : 0;
        unsigned cm = __ballot_sync(0xffffffffu, cv > 0);
        unsigned pm = __ballot_sync(0xffffffffu, pv > 0);
        if (lane == 0) {
            g_cbits[b * SW + w] = cm;
            g_pbits[b * SW + w] = pm;
            degc += __popc(cm);
            degp += __popc(pm);
        }
    }
    __shared__ int sdc[8], sdp[8];
    if (lane == 0) { sdc[wid] = degc; sdp[wid] = degp; }
    __syncthreads();
    if (threadIdx.x == 0) {
        int dc = 0, dp = 0;
        for (int i = 0; i < 8; i++) { dc += sdc[i]; dp += sdp[i]; }
        g_inv2[b] = make_float2(dc > 0 ? 1.f / (float)dc : 0.f,
                                dp > 0 ? 1.f / (float)dp : 0.f);
    }
}

// ---- K1 ----
__global__ void k1_h1(const float* __restrict__ Rfeat, const float* __restrict__ W1,
                      const float* __restrict__ a) {
    int h = blockIdx.x / R_N, r = blockIdx.x % R_N, f = threadIdx.x;
    const float* w  = W1 + (size_t)h * FD * FD;
    const float* rf = Rfeat + r * FD;
    float acc = 0.f;
    #pragma unroll 8
    for (int k = 0; k < FD; k++) acc = fmaf(rf[k], w[k * FD + f], acc);
    g_h1[(h * R_N + r) * FD + f] = acc;
    __shared__ float sh[128];
    sh[f] = acc * a[h * 2 * FD + f];
    __syncthreads();
    for (int st = 64; st > 0; st >>= 1) {
        if (f < st) sh[f] += sh[f + st];
        __syncthreads();
    }
    if (f == 0) g_h1a[h * R_N + r] = sh[0];
}

// ---- K2: h2 = Sfeat @ W2[h] ----
__global__ __launch_bounds__(256) void k2_h2(const float* __restrict__ Sfeat,
                                             const float* __restrict__ W2) {
    const int h = blockIdx.y;
    const int s0 = blockIdx.x * 64;
    const int tid = threadIdx.x;
    const int tx = tid & 31;
    const int ty = tid >> 5;
    __shared__ float sf[FD][68];
    for (int i = tid; i < 64 * FD; i += 256) {
        int sl = i >> 7, k = i & 127;
        int s = s0 + sl;
        sf[k][sl] = (s < S_N) ? Sfeat[(size_t)s * FD + k] : 0.f;
    }
    __syncthreads();
    float acc[8][4];
    #pragma unroll
    for (int i = 0; i < 8; i++)
        #pragma unroll
        for (int j = 0; j < 4; j++) acc[i][j] = 0.f;
    const float4* w4 = (const float4*)(W2 + (size_t)h * FD * FD);
    #pragma unroll 4
    for (int k = 0; k < FD; k++) {
        float4 wv = w4[k * 32 + tx];
        float4 sa = *(const float4*)&sf[k][ty * 8];
        float4 sb = *(const float4*)&sf[k][ty * 8 + 4];
        float sv[8] = {sa.x, sa.y, sa.z, sa.w, sb.x, sb.y, sb.z, sb.w};
        #pragma unroll
        for (int i = 0; i < 8; i++) {
            acc[i][0] = fmaf(sv[i], wv.x, acc[i][0]);
            acc[i][1] = fmaf(sv[i], wv.y, acc[i][1]);
            acc[i][2] = fmaf(sv[i], wv.z, acc[i][2]);
            acc[i][3] = fmaf(sv[i], wv.w, acc[i][3]);
        }
    }
    #pragma unroll
    for (int i = 0; i < 8; i++) {
        int s = s0 + ty * 8 + i;
        if (s < S_N) {
            float4 o = make_float4(acc[i][0], acc[i][1], acc[i][2], acc[i][3]);
            *(float4*)&g_h2[((size_t)h * S_N + s) * FD + tx * 4] = o;
        }
    }
}

// ---- K45: attention + v partials (profiled slot #4) ----
__global__ __launch_bounds__(256) void k45_attv(const int* __restrict__ inter,
                                                const float* __restrict__ a) {
    const int h = blockIdx.y, tile = blockIdx.x, s0 = tile * 128;
    const int tid = threadIdx.x, lane = tid & 31, w = tid >> 5;
    __shared__ float attS[128][17];
    const float* a2 = a + h * 2 * FD + FD;
    float a2v[4];
    #pragma unroll
    for (int i = 0; i < 4; i++) a2v[i] = a2[lane + 32 * i];
    for (int it = 0; it < 16; it++) {
        int sl = w * 16 + it;
        int s = s0 + sl;
        if (s < S_N) {
            const float* row = &g_h2[((size_t)h * S_N + s) * FD];
            float d = 0.f;
            #pragma unroll
            for (int i = 0; i < 4; i++) d = fmaf(row[lane + 32 * i], a2v[i], d);
            #pragma unroll
            for (int o = 16; o > 0; o >>= 1) d += __shfl_xor_sync(0xffffffffu, d, o);
            float z = NEG;
            if (lane < R_N && inter[s * R_N + lane] > 0)
                z = lrelu(d + g_h1a[h * R_N + lane]);
            float mx = z;
            #pragma unroll
            for (int o = 8; o > 0; o >>= 1) mx = fmaxf(mx, __shfl_xor_sync(0xffffffffu, mx, o));
            float ex = (lane < R_N) ? expf(z - mx) : 0.f;
            float sm = ex;
            #pragma unroll
            for (int o = 8; o > 0; o >>= 1) sm += __shfl_xor_sync(0xffffffffu, sm, o);
            if (lane < R_N) {
                float av = ex / sm;
                attS[sl][lane] = av;
                g_att[((h * S_N) + s) * R_N + lane] = av;
            }
        } else if (lane < R_N) {
            attS[sl][lane] = 0.f;
        }
    }
    __syncthreads();
    const int f = tid & 127, half = tid >> 7;
    float acc[R_N];
    #pragma unroll
    for (int r = 0; r < R_N; r++) acc[r] = 0.f;
    const int base = half * 64;
    for (int si = 0; si < 64; si++) {
        int s = s0 + base + si;
        if (s >= S_N) break;
        float v = g_h2[((size_t)h * S_N + s) * FD + f];
        #pragma unroll
        for (int r = 0; r < R_N; r++) acc[r] = fmaf(attS[base + si][r], v, acc[r]);
    }
    const int chunk = tile * 2 + half;
    #pragma unroll
    for (int r = 0; r < R_N; r++)
        g_vpart[((chunk * H_N * R_N) + h * R_N + r) * FD + f] = acc[r];
}

// ---- K3w: (4096*W)^T[s][b] e4m3 via smem transpose ----
__global__ __launch_bounds__(256) void k3w_t8() {
    __shared__ __align__(16) unsigned char st[32][256];
    const int s0 = blockIdx.x * 32, b0 = blockIdx.y * 256;
    const int t = threadIdx.x;
    const int b = b0 + t;
    unsigned cw = 0, pw = 0;
    float2 iv = make_float2(0.f, 0.f);
    if (s0 < S_N) {
        cw = g_cbits[(size_t)b * SW + (s0 >> 5)];
        pw = g_pbits[(size_t)b * SW + (s0 >> 5)];
        iv = g_inv2[b];
    }
    float ic = iv.x * 4096.f, ip = iv.y * 4096.f;
    #pragma unroll
    for (int sl = 0; sl < 32; sl++) {
        float v = ((cw >> sl) & 1u) ? ic : 0.f;
        if ((pw >> sl) & 1u) v += ip;
        st[sl][t] = (unsigned char)f8pack(v, 0.f);   // low byte = v
    }
    __syncthreads();
    #pragma unroll
    for (int j = 0; j < 2; j++) {
        int idx = t + j * 256;
        int row = idx >> 4, sg = idx & 15;
        uint4 val = *(const uint4*)&st[row][sg * 16];
        *(uint4*)&g_wbt8[(size_t)(s0 + row) * B_N + b0 + sg * 16] = val;
    }
}

// ---- K3y: (16*y)^T[h][f][b] e4m3 ----  (exactly H_N*FD*(B_N/16) threads)
__global__ void k3y8(const int* __restrict__ src) {
    int idx = blockIdx.x * 256 + threadIdx.x;   // 256 blocks x 256 = 65536
    int f = idx & 127;
    int bg = (idx >> 7) & 127;
    int h = idx >> 14;                           // 0..3
    __align__(16) unsigned short o8[8];
    #pragma unroll
    for (int j = 0; j < 8; j++) {
        int bb = bg * 16 + 2 * j;
        float v0 = g_h2[((size_t)h * S_N + src[bb]) * FD + f] * 16.f;
        float v1 = g_h2[((size_t)h * S_N + src[bb + 1]) * FD + f] * 16.f;
        o8[j] = f8pack(v0, v1);
    }
    *(uint4*)&g_ybt8[((size_t)h * FD + f) * B_N + bg * 16] = *(const uint4*)o8;
}

// ---- K5b ----
__global__ void k5b_bnv(const float* __restrict__ g1, const float* __restrict__ b1) {
    int i = blockIdx.x * blockDim.x + threadIdx.x;
    if (i >= H_N * FD) return;
    int h = i / FD, f = i % FD;
    float x[R_N];
    float m = 0.f;
    #pragma unroll
    for (int r = 0; r < R_N; r++) {
        float t = 0.f;
        for (int c = 0; c < NCH; c++)
            t += g_vpart[((c * H_N * R_N) + h * R_N + r) * FD + f];
        x[r] = t;
        m += t;
    }
    m *= (1.f / R_N);
    float var = 0.f;
    #pragma unroll
    for (int r = 0; r < R_N; r++) { float d = x[r] - m; var = fmaf(d, d, var); }
    var *= (1.f / R_N);
    float inv = rsqrtf(var + 1e-5f);
    float gg = g1[i], bb = b1[i];
    #pragma unroll
    for (int r = 0; r < R_N; r++)
        g_v[((h * R_N) + r) * FD + f] = lrelu((x[r] - m) * inv * gg + bb);
}

// ---- K6: fp8 m16n8k32 GEMM (IntraNC) + fp32 InterRC + fused BN partials ----
#define K6_SMEM 57856
__device__ __forceinline__ void k6_stage(char* sm, int c, int h, int s0, int tid) {
    int buf = c & 1;
    uint32_t ab = su(sm) + buf * 10240;
    uint32_t bb = su(sm) + 20480 + buf * 10240;
    #pragma unroll
    for (int j = 0; j < 2; j++) {
        int idx = tid + j * 256;
        int row = idx >> 2, sg = idx & 3;
        CP16(ab + row * 80 + sg * 16, &g_wbt8[(size_t)(s0 + row) * B_N + c * 64 + sg * 16]);
        CP16(bb + row * 80 + sg * 16, &g_ybt8[((size_t)h * FD + row) * B_N + c * 64 + sg * 16]);
    }
    CPCOMMIT;
}

__global__ __launch_bounds__(256, 2) void k6_f8() {
    extern __shared__ __align__(16) char sm6[];
    float (*attsh)[17] = (float(*)[17])(sm6 + 40960);
    float (*h1sh)[128] = (float(*)[128])(sm6 + 49664);

    const int h = blockIdx.y, tile = blockIdx.x, s0 = tile * 128;
    const int tid = threadIdx.x, lane = tid & 31, w = tid >> 5;
    const int wm = w >> 1, wn = w & 1;     // 4m x 2n warps: 32s x 64f each
    const int g = lane >> 2, tg = lane & 3;

    for (int i = tid; i < 128 * R_N; i += 256) {
        int sl = i >> 4, r = i & 15;
        int s = s0 + sl;
        attsh[sl][r] = (s < S_N) ? g_att[((h * S_N) + s) * R_N + r] : 0.f;
    }
    for (int i = tid; i < R_N * FD; i += 256)
        h1sh[i >> 7][i & 127] = g_h1[h * R_N * FD + i];

    float acc[2][8][4] = {};
    k6_stage(sm6, 0, h, s0, tid);

    const int lrow = lane & 15;
    const int lcol = (lane >> 4) * 16;

    for (int c = 0; c < 32; c++) {
        const int buf = c & 1;
        CPWAIT0;
        __syncthreads();
        if (c < 31) k6_stage(sm6, c + 1, h, s0, tid);
        uint32_t abase = su(sm6) + buf * 10240;
        uint32_t bbase = su(sm6) + 20480 + buf * 10240;
        #pragma unroll
        for (int z = 0; z < 2; z++) {
            unsigned A[2][4];
            #pragma unroll
            for (int im = 0; im < 2; im++)
                ldmx4(A[im][0], A[im][1], A[im][2], A[im][3],
                      abase + (wm * 32 + im * 16 + lrow) * 80 + z * 32 + lcol);
            unsigned Bf[8][2];
            #pragma unroll
            for (int q = 0; q < 4; q++) {
                unsigned r0, r1, r2, r3;
                ldmx4(r0, r1, r2, r3,
                      bbase + (wn * 64 + q * 16 + lrow) * 80 + z * 32 + lcol);
                Bf[q * 2][0] = r0;     Bf[q * 2][1] = r2;
                Bf[q * 2 + 1][0] = r1; Bf[q * 2 + 1][1] = r3;
            }
            #pragma unroll
            for (int im = 0; im < 2; im++)
                #pragma unroll
                for (int in = 0; in < 8; in++)
                    mma_f8(acc[im][in], A[im], Bf[in]);
        }
    }

    const float SCL = 1.f / 65536.f;   // undo 4096 * 16
    #pragma unroll
    for (int im = 0; im < 2; im++)
        #pragma unroll
        for (int in = 0; in < 8; in++)
            #pragma unroll
            for (int j = 0; j < 4; j++) acc[im][in][j] *= SCL;

    // InterRC in fp32
    const int sb = wm * 32 + g;
    const int fb = wn * 64 + 2 * tg;
    #pragma unroll
    for (int r = 0; r < R_N; r++) {
        float a00 = attsh[sb][r],      a01 = attsh[sb + 8][r];
        float a10 = attsh[sb + 16][r], a11 = attsh[sb + 24][r];
        #pragma unroll
        for (int in = 0; in < 8; in++) {
            float hv0 = h1sh[r][fb + in * 8];
            float hv1 = h1sh[r][fb + in * 8 + 1];
            acc[0][in][0] = fmaf(a00, hv0, acc[0][in][0]);
            acc[0][in][1] = fmaf(a00, hv1, acc[0][in][1]);
            acc[0][in][2] = fmaf(a01, hv0, acc[0][in][2]);
            acc[0][in][3] = fmaf(a01, hv1, acc[0][in][3]);
            acc[1][in][0] = fmaf(a10, hv0, acc[1][in][0]);
            acc[1][in][1] = fmaf(a10, hv1, acc[1][in][1]);
            acc[1][in][2] = fmaf(a11, hv0, acc[1][in][2]);
            acc[1][in][3] = fmaf(a11, hv1, acc[1][in][3]);
        }
    }
    // store u
    #pragma unroll
    for (int im = 0; im < 2; im++)
        #pragma unroll
        for (int hf = 0; hf < 2; hf++) {
            int s = s0 + wm * 32 + im * 16 + g + hf * 8;
            if (s < S_N) {
                float* up = &g_u[((size_t)h * S_N + s) * FD + fb];
                #pragma unroll
                for (int in = 0; in < 8; in++) {
                    float2 o = make_float2(acc[im][in][hf * 2], acc[im][in][hf * 2 + 1]);
                    *(float2*)(up + in * 8) = o;
                }
            }
        }
    // fused BN column partials
    __syncthreads();
    float* rs = (float*)sm6;
    float* rq = rs + 512;
    #pragma unroll
    for (int in = 0; in < 8; in++)
        #pragma unroll
        for (int half = 0; half < 2; half++) {
            float a0 = acc[0][in][half],     a1 = acc[0][in][2 + half];
            float a2 = acc[1][in][half],     a3 = acc[1][in][2 + half];
            float sm_ = a0 + a1 + a2 + a3;
            float sq_ = a0 * a0 + a1 * a1 + a2 * a2 + a3 * a3;
            #pragma unroll
            for (int o = 4; o <= 16; o <<= 1) {
                sm_ += __shfl_xor_sync(0xffffffffu, sm_, o);
                sq_ += __shfl_xor_sync(0xffffffffu, sq_, o);
            }
            if (lane < 4) {
                int f = wn * 64 + in * 8 + 2 * lane + half;
                rs[wm * 128 + f] = sm_;
                rq[wm * 128 + f] = sq_;
            }
        }
    __syncthreads();
    if (tid < 128) {
        float s4 = rs[tid] + rs[128 + tid] + rs[256 + tid] + rs[384 + tid];
        float q4 = rq[tid] + rq[128 + tid] + rq[256 + tid] + rq[384 + tid];
        g_upsum[tile * H_N * FD + h * FD + tid] = s4;
        g_upsq [tile * H_N * FD + h * FD + tid] = q4;
    }
}

// ---- K7b ----
__global__ void k7b_bnu(const float* __restrict__ g2, const float* __restrict__ b2) {
    int i = blockIdx.x * blockDim.x + threadIdx.x;
    if (i >= H_N * FD) return;
    float sm = 0.f, sq = 0.f;
    for (int c = 0; c < 79; c++) {
        sm += g_upsum[c * H_N * FD + i];
        sq += g_upsq [c * H_N * FD + i];
    }
    float mean = sm / (float)S_N;
    float var = sq / (float)S_N - mean * mean;
    float al = g2[i] * rsqrtf(var + 1e-5f);
    g_alpha[i] = al;
    g_beta[i]  = b2[i] - mean * al;
}

// ---- K8 ----
__global__ void k8_out(const int* __restrict__ inter, const float* __restrict__ outW,
                       float* __restrict__ out) {
    int s = blockIdx.x * 8 + (threadIdx.x >> 5);
    int lane = threadIdx.x & 31;
    if (s >= S_N) return;
    float un[H_N][4];
    #pragma unroll
    for (int h = 0; h < H_N; h++)
        #pragma unroll
        for (int i = 0; i < 4; i++) {
            int f = lane + 32 * i;
            float x = g_u[((size_t)h * S_N + s) * FD + f];
            un[h][i] = lrelu(fmaf(x, g_alpha[h * FD + f], g_beta[h * FD + f]));
        }
    float hf = 0.f;
    #pragma unroll
    for (int h = 0; h < H_N; h++)
        for (int r = 0; r < R_N; r++) {
            float d = 0.f;
            #pragma unroll
            for (int i = 0; i < 4; i++) {
                int f = lane + 32 * i;
                d = fmaf(un[h][i], g_v[((h * R_N) + r) * FD + f], d);
            }
            #pragma unroll
            for (int o = 16; o > 0; o >>= 1) d += __shfl_xor_sync(0xffffffffu, d, o);
            float ho = elu(d);
            if (lane < C_N) hf = fmaf(ho, outW[(h * R_N + r) * C_N + lane], hf);
        }
    int adj = (lane < R_N) ? inter[s * R_N + lane] : 0;
    unsigned m = __ballot_sync(0xffffffffu, (lane < R_N) && adj > 0);
    int deg = __popc(m);
    float att = (deg > 0) ? (adj > 0 ? 1.f / (float)deg : 0.f) : (1.f / (float)R_N);
    float t = att * hf;
    t = elu(t);
    t = elu(t);
    float z = (lane < C_N) ? t : -3.4e38f;
    float mx = z;
    #pragma unroll
    for (int o = 8; o > 0; o >>= 1) mx = fmaxf(mx, __shfl_xor_sync(0xffffffffu, mx, o));
    float ex = (lane < C_N) ? expf(z - mx) : 0.f;
    float sm = ex;
    #pragma unroll
    for (int o = 8; o > 0; o >>= 1) sm += __shfl_xor_sync(0xffffffffu, sm, o);
    if (lane < C_N) out[s * C_N + lane] = (z - mx) - logf(sm);
}

// ---- launch ----
extern "C" void kernel_launch(void* const* d_in, const int* in_sizes, int n_in,
                              void* d_out, int out_size) {
    const int*   inter = (const int*)d_in[0];
    const int*   city  = (const int*)d_in[1];
    const int*   prov  = (const int*)d_in[2];
    const int*   src   = (const int*)d_in[3];
    const float* Sfeat = (const float*)d_in[4];
    const float* Rfeat = (const float*)d_in[5];
    const float* W1    = (const float*)d_in[6];
    const float* W2    = (const float*)d_in[7];
    const float* a     = (const float*)d_in[8];
    const float* bn1g  = (const float*)d_in[11];
    const float* bn1b  = (const float*)d_in[12];
    const float* bn2g  = (const float*)d_in[13];
    const float* bn2b  = (const float*)d_in[14];
    const float* outW  = (const float*)d_in[15];
    float* out = (float*)d_out;

    cudaFuncSetAttribute(k6_f8, cudaFuncAttributeMaxDynamicSharedMemorySize, K6_SMEM);

    k3_bits<<<B_N, 256>>>(city, prov, src);
    k1_h1<<<H_N * R_N, 128>>>(Rfeat, W1, a);
    k2_h2<<<dim3((S_N + 63) / 64, H_N), 256>>>(Sfeat, W2);
    k45_attv<<<dim3(79, H_N), 256>>>(inter, a);        // profiled slot #4
    k3w_t8<<<dim3(SP / 32, B_N / 256), 256>>>();
    k3y8<<<256, 256>>>(src);
    k5b_bnv<<<(H_N * FD + 127) / 128, 128>>>(bn1g, bn1b);
    k6_f8<<<dim3(79, H_N), 256, K6_SMEM>>>();
    k7b_bnu<<<(H_N * FD + 127) / 128, 128>>>(bn2g, bn2b);
    k8_out<<<(S_N + 7) / 8, 256>>>(inter, outW, out);
}

// round 9
// speedup vs baseline: 1.4213x; 1.3199x over previous
#include <cuda_runtime.h>
#include <cuda_bf16.h>
#include <cuda_fp8.h>
#include <math.h>
#include <stdint.h>

#define S_N 10000
#define R_N 16
#define FD 128
#define H_N 4
#define B_N 2048
#define C_N 16
#define NEG (-9e15f)
#define SW 313
#define SP 10112
#define NCH 158

__device__ float g_h1[H_N * R_N * FD];
__device__ float g_h1a[H_N * R_N];
__device__ float g_h2[(size_t)H_N * S_N * FD];
__device__ unsigned g_cbits[B_N * SW];
__device__ unsigned g_pbits[B_N * SW];
__device__ float2 g_inv2[B_N];
__device__ unsigned char g_wbt8[(size_t)SP * B_N];       // (4096*W)^T [s][b] e4m3
__device__ unsigned char g_ybt8[(size_t)H_N * FD * B_N]; // (16*y)^T [h][f][b] e4m3
__device__ float g_att[H_N * S_N * R_N];
__device__ float g_vpart[NCH * H_N * R_N * FD];
__device__ float g_vsum[2 * H_N * R_N * FD];
__device__ float g_v[H_N * R_N * FD];
__device__ float g_u[(size_t)H_N * S_N * FD];
__device__ float g_upsum[79 * H_N * FD];
__device__ float g_upsq[79 * H_N * FD];
__device__ float g_alpha[H_N * FD];
__device__ float g_beta[H_N * FD];

__device__ __forceinline__ float lrelu(float x) { return x > 0.f ? x : 0.2f * x; }
__device__ __forceinline__ float elu(float x)   { return x > 0.f ? x : expm1f(x); }
__device__ __forceinline__ unsigned su(const void* p) {
    return (unsigned)__cvta_generic_to_shared(p);
}
__device__ __forceinline__ void ldmx4(unsigned& r0, unsigned& r1, unsigned& r2,
                                      unsigned& r3, unsigned addr) {
    asm volatile("ldmatrix.sync.aligned.m8n8.x4.shared.b16 {%0,%1,%2,%3},[%4];"
                 : "=r"(r0), "=r"(r1), "=r"(r2), "=r"(r3) : "r"(addr));
}
__device__ __forceinline__ void mma_f8(float c[4], const unsigned a[4], const unsigned b[2]) {
    asm volatile(
        "mma.sync.aligned.m16n8k32.row.col.f32.e4m3.e4m3.f32 "
        "{%0,%1,%2,%3},{%4,%5,%6,%7},{%8,%9},{%0,%1,%2,%3};"
        : "+f"(c[0]), "+f"(c[1]), "+f"(c[2]), "+f"(c[3])
        : "r"(a[0]), "r"(a[1]), "r"(a[2]), "r"(a[3]), "r"(b[0]), "r"(b[1]));
}
__device__ __forceinline__ unsigned short f8pack(float lo, float hi) {
    unsigned short p;
    asm("cvt.rn.satfinite.e4m3x2.f32 %0, %1, %2;" : "=h"(p) : "f"(hi), "f"(lo));
    return p;
}
#define CP16(d, s) asm volatile("cp.async.cg.shared.global [%0],[%1],16;" ::"r"(d), "l"(s))
#define CPCOMMIT   asm volatile("cp.async.commit_group;")

// ---- K3: bitpack adjacency + degrees ----
__global__ void k3_bits(const int* __restrict__ city, const int* __restrict__ prov,
                        const int* __restrict__ src) {
    int b = blockIdx.x;
    int n = src[b];
    const int* crow = city + (size_t)n * S_N;
    const int* prow = prov + (size_t)n * S_N;
    int lane = threadIdx.x & 31, wid = threadIdx.x >> 5;
    int degc = 0, degp = 0;
    for (int w = wid; w < SW; w += 8) {
        int s = w * 32 + lane;
        bool inb = s < S_N;
        int cv = inb ? crow[s] : 0;
        int pv = inb ? prow[s] : 0;
        unsigned cm = __ballot_sync(0xffffffffu, cv > 0);
        unsigned pm = __ballot_sync(0xffffffffu, pv > 0);
        if (lane == 0) {
            g_cbits[b * SW + w] = cm;
            g_pbits[b * SW + w] = pm;
            degc += __popc(cm);
            degp += __popc(pm);
        }
    }
    __shared__ int sdc[8], sdp[8];
    if (lane == 0) { sdc[wid] = degc; sdp[wid] = degp; }
    __syncthreads();
    if (threadIdx.x == 0) {
        int dc = 0, dp = 0;
        for (int i = 0; i < 8; i++) { dc += sdc[i]; dp += sdp[i]; }
        g_inv2[b] = make_float2(dc > 0 ? 1.f / (float)dc : 0.f,
                                dp > 0 ? 1.f / (float)dp : 0.f);
    }
}

// ---- K3w: (4096*W)^T[s][b] e4m3 via smem transpose ----
__global__ __launch_bounds__(256) void k3w_t8() {
    __shared__ __align__(16) unsigned char st[32][256];
    const int s0 = blockIdx.x * 32, b0 = blockIdx.y * 256;
    const int t = threadIdx.x;
    const int b = b0 + t;
    unsigned cw = 0, pw = 0;
    float2 iv = make_float2(0.f, 0.f);
    if (s0 < S_N) {
        cw = g_cbits[(size_t)b * SW + (s0 >> 5)];
        pw = g_pbits[(size_t)b * SW + (s0 >> 5)];
        iv = g_inv2[b];
    }
    float ic = iv.x * 4096.f, ip = iv.y * 4096.f;
    #pragma unroll
    for (int sl = 0; sl < 32; sl++) {
        float v = ((cw >> sl) & 1u) ? ic : 0.f;
        if ((pw >> sl) & 1u) v += ip;
        st[sl][t] = (unsigned char)f8pack(v, 0.f);
    }
    __syncthreads();
    #pragma unroll
    for (int j = 0; j < 2; j++) {
        int idx = t + j * 256;
        int row = idx >> 4, sg = idx & 15;
        uint4 val = *(const uint4*)&st[row][sg * 16];
        *(uint4*)&g_wbt8[(size_t)(s0 + row) * B_N + b0 + sg * 16] = val;
    }
}

// ---- K1 ----
__global__ void k1_h1(const float* __restrict__ Rfeat, const float* __restrict__ W1,
                      const float* __restrict__ a) {
    int h = blockIdx.x / R_N, r = blockIdx.x % R_N, f = threadIdx.x;
    const float* w  = W1 + (size_t)h * FD * FD;
    const float* rf = Rfeat + r * FD;
    float acc = 0.f;
    #pragma unroll 8
    for (int k = 0; k < FD; k++) acc = fmaf(rf[k], w[k * FD + f], acc);
    g_h1[(h * R_N + r) * FD + f] = acc;
    __shared__ float sh[128];
    sh[f] = acc * a[h * 2 * FD + f];
    __syncthreads();
    for (int st = 64; st > 0; st >>= 1) {
        if (f < st) sh[f] += sh[f + st];
        __syncthreads();
    }
    if (f == 0) g_h1a[h * R_N + r] = sh[0];
}

// ---- K2: h2 = Sfeat @ W2[h] (profiled slot #4) ----
__global__ __launch_bounds__(256) void k2_h2(const float* __restrict__ Sfeat,
                                             const float* __restrict__ W2) {
    const int h = blockIdx.y;
    const int s0 = blockIdx.x * 64;
    const int tid = threadIdx.x;
    const int tx = tid & 31;
    const int ty = tid >> 5;
    __shared__ float sf[FD][68];
    for (int i = tid; i < 64 * FD; i += 256) {
        int sl = i >> 7, k = i & 127;
        int s = s0 + sl;
        sf[k][sl] = (s < S_N) ? Sfeat[(size_t)s * FD + k] : 0.f;
    }
    __syncthreads();
    float acc[8][4];
    #pragma unroll
    for (int i = 0; i < 8; i++)
        #pragma unroll
        for (int j = 0; j < 4; j++) acc[i][j] = 0.f;
    const float4* w4 = (const float4*)(W2 + (size_t)h * FD * FD);
    #pragma unroll 4
    for (int k = 0; k < FD; k++) {
        float4 wv = w4[k * 32 + tx];
        float4 sa = *(const float4*)&sf[k][ty * 8];
        float4 sb = *(const float4*)&sf[k][ty * 8 + 4];
        float sv[8] = {sa.x, sa.y, sa.z, sa.w, sb.x, sb.y, sb.z, sb.w};
        #pragma unroll
        for (int i = 0; i < 8; i++) {
            acc[i][0] = fmaf(sv[i], wv.x, acc[i][0]);
            acc[i][1] = fmaf(sv[i], wv.y, acc[i][1]);
            acc[i][2] = fmaf(sv[i], wv.z, acc[i][2]);
            acc[i][3] = fmaf(sv[i], wv.w, acc[i][3]);
        }
    }
    #pragma unroll
    for (int i = 0; i < 8; i++) {
        int s = s0 + ty * 8 + i;
        if (s < S_N) {
            float4 o = make_float4(acc[i][0], acc[i][1], acc[i][2], acc[i][3]);
            *(float4*)&g_h2[((size_t)h * S_N + s) * FD + tx * 4] = o;
        }
    }
}

// ---- K3y: (16*y)^T[h][f][b] e4m3 ----
__global__ void k3y8(const int* __restrict__ src) {
    int idx = blockIdx.x * 256 + threadIdx.x;   // 256 blocks x 256 = 65536
    int f = idx & 127;
    int bg = (idx >> 7) & 127;
    int h = idx >> 14;
    __align__(16) unsigned short o8[8];
    #pragma unroll
    for (int j = 0; j < 8; j++) {
        int bb = bg * 16 + 2 * j;
        float v0 = g_h2[((size_t)h * S_N + src[bb]) * FD + f] * 16.f;
        float v1 = g_h2[((size_t)h * S_N + src[bb + 1]) * FD + f] * 16.f;
        o8[j] = f8pack(v0, v1);
    }
    *(uint4*)&g_ybt8[((size_t)h * FD + f) * B_N + bg * 16] = *(const uint4*)o8;
}

// ---- K45: attention + v partials, s-tile 64, grid (158, H) ----
__global__ __launch_bounds__(256) void k45_attv(const int* __restrict__ inter,
                                                const float* __restrict__ a) {
    const int h = blockIdx.y, tile = blockIdx.x, s0 = tile * 64;
    const int tid = threadIdx.x, lane = tid & 31, w = tid >> 5;
    __shared__ float attS[64][17];
    __shared__ float red[R_N * 128];
    const float* a2 = a + h * 2 * FD + FD;
    float a2v[4];
    #pragma unroll
    for (int i = 0; i < 4; i++) a2v[i] = a2[lane + 32 * i];
    // phase 1: 8 warps x 8 rows
    #pragma unroll
    for (int it = 0; it < 8; it++) {
        int sl = w * 8 + it;
        int s = s0 + sl;
        if (s < S_N) {
            const float* row = &g_h2[((size_t)h * S_N + s) * FD];
            float d = 0.f;
            #pragma unroll
            for (int i = 0; i < 4; i++) d = fmaf(row[lane + 32 * i], a2v[i], d);
            #pragma unroll
            for (int o = 16; o > 0; o >>= 1) d += __shfl_xor_sync(0xffffffffu, d, o);
            float z = NEG;
            if (lane < R_N && inter[s * R_N + lane] > 0)
                z = lrelu(d + g_h1a[h * R_N + lane]);
            float mx = z;
            #pragma unroll
            for (int o = 8; o > 0; o >>= 1) mx = fmaxf(mx, __shfl_xor_sync(0xffffffffu, mx, o));
            float ex = (lane < R_N) ? expf(z - mx) : 0.f;
            float sm = ex;
            #pragma unroll
            for (int o = 8; o > 0; o >>= 1) sm += __shfl_xor_sync(0xffffffffu, sm, o);
            if (lane < R_N) {
                float av = ex / sm;
                attS[sl][lane] = av;
                g_att[((h * S_N) + s) * R_N + lane] = av;
            }
        } else if (lane < R_N) {
            attS[sl][lane] = 0.f;
        }
    }
    __syncthreads();
    // phase 2: 2 s-halves x 128 f
    const int f = tid & 127, half = tid >> 7;
    float acc[R_N];
    #pragma unroll
    for (int r = 0; r < R_N; r++) acc[r] = 0.f;
    const int base = half * 32;
    for (int si = 0; si < 32; si++) {
        int s = s0 + base + si;
        if (s >= S_N) break;
        float v = g_h2[((size_t)h * S_N + s) * FD + f];
        #pragma unroll
        for (int r = 0; r < R_N; r++) acc[r] = fmaf(attS[base + si][r], v, acc[r]);
    }
    if (half == 1) {
        #pragma unroll
        for (int r = 0; r < R_N; r++) red[r * 128 + f] = acc[r];
    }
    __syncthreads();
    if (half == 0) {
        #pragma unroll
        for (int r = 0; r < R_N; r++)
            g_vpart[((tile * H_N * R_N) + h * R_N + r) * FD + f] =
                acc[r] + red[r * 128 + f];
    }
}

// ---- K5r: reduce vpart chunks (parallel, coalesced) ----
__global__ void k5r() {
    int h = blockIdx.x >> 4, r = blockIdx.x & 15;   // grid (64, 2)
    int part = blockIdx.y, f = threadIdx.x;
    int c0 = part * 79;
    float t = 0.f;
    #pragma unroll 4
    for (int c = 0; c < 79; c++)
        t += g_vpart[(((c0 + c) * H_N * R_N) + h * R_N + r) * FD + f];
    g_vsum[((part * H_N + h) * R_N + r) * FD + f] = t;
}

// ---- K5b2: BN over R + lrelu -> g_v ----
__global__ void k5b2(const float* __restrict__ g1, const float* __restrict__ b1) {
    int i = blockIdx.x * blockDim.x + threadIdx.x;
    if (i >= H_N * FD) return;
    int h = i / FD, f = i % FD;
    float x[R_N];
    float m = 0.f;
    #pragma unroll
    for (int r = 0; r < R_N; r++) {
        float t = g_vsum[((0 * H_N + h) * R_N + r) * FD + f]
                + g_vsum[((1 * H_N + h) * R_N + r) * FD + f];
        x[r] = t;
        m += t;
    }
    m *= (1.f / R_N);
    float var = 0.f;
    #pragma unroll
    for (int r = 0; r < R_N; r++) { float d = x[r] - m; var = fmaf(d, d, var); }
    var *= (1.f / R_N);
    float inv = rsqrtf(var + 1e-5f);
    float gg = g1[i], bb = b1[i];
    #pragma unroll
    for (int r = 0; r < R_N; r++)
        g_v[((h * R_N) + r) * FD + f] = lrelu((x[r] - m) * inv * gg + bb);
}

// ---- K6: fp8 GEMM, 4-stage cp.async pipeline + fp32 InterRC + BN partials ----
// smem: A 4x10240 @0 | B 4x10240 @40960 | attsh @81920 (8704) | h1sh @90624 (8192)
#define K6_SMEM 98816
__device__ __forceinline__ void k6_stage(char* sm, int c, int h, int s0, int tid) {
    int st = c & 3;
    uint32_t ab = su(sm) + st * 10240;
    uint32_t bb = su(sm) + 40960 + st * 10240;
    #pragma unroll
    for (int j = 0; j < 2; j++) {
        int idx = tid + j * 256;
        int row = idx >> 2, sg = idx & 3;
        CP16(ab + row * 80 + sg * 16, &g_wbt8[(size_t)(s0 + row) * B_N + c * 64 + sg * 16]);
        CP16(bb + row * 80 + sg * 16, &g_ybt8[((size_t)h * FD + row) * B_N + c * 64 + sg * 16]);
    }
    CPCOMMIT;
}

__global__ __launch_bounds__(256, 2) void k6_f8() {
    extern __shared__ __align__(16) char sm6[];
    float (*attsh)[17] = (float(*)[17])(sm6 + 81920);
    float (*h1sh)[128] = (float(*)[128])(sm6 + 90624);

    const int h = blockIdx.y, tile = blockIdx.x, s0 = tile * 128;
    const int tid = threadIdx.x, lane = tid & 31, w = tid >> 5;
    const int wm = w >> 1, wn = w & 1;
    const int g = lane >> 2, tg = lane & 3;

    for (int i = tid; i < 128 * R_N; i += 256) {
        int sl = i >> 4, r = i & 15;
        int s = s0 + sl;
        attsh[sl][r] = (s < S_N) ? g_att[((h * S_N) + s) * R_N + r] : 0.f;
    }
    for (int i = tid; i < R_N * FD; i += 256)
        h1sh[i >> 7][i & 127] = g_h1[h * R_N * FD + i];

    float acc[2][8][4] = {};
    k6_stage(sm6, 0, h, s0, tid);
    k6_stage(sm6, 1, h, s0, tid);
    k6_stage(sm6, 2, h, s0, tid);

    const int lrow = lane & 15;
    const int lcol = (lane >> 4) * 16;

    for (int c = 0; c < 32; c++) {
        if (c < 30)      { asm volatile("cp.async.wait_group 2;"); }
        else if (c == 30){ asm volatile("cp.async.wait_group 1;"); }
        else             { asm volatile("cp.async.wait_group 0;"); }
        __syncthreads();
        if (c + 3 < 32) k6_stage(sm6, c + 3, h, s0, tid);
        const int buf = c & 3;
        uint32_t abase = su(sm6) + buf * 10240;
        uint32_t bbase = su(sm6) + 40960 + buf * 10240;
        #pragma unroll
        for (int z = 0; z < 2; z++) {
            unsigned A[2][4];
            #pragma unroll
            for (int im = 0; im < 2; im++)
                ldmx4(A[im][0], A[im][1], A[im][2], A[im][3],
                      abase + (wm * 32 + im * 16 + lrow) * 80 + z * 32 + lcol);
            unsigned Bf[8][2];
            #pragma unroll
            for (int q = 0; q < 4; q++) {
                unsigned r0, r1, r2, r3;
                ldmx4(r0, r1, r2, r3,
                      bbase + (wn * 64 + q * 16 + lrow) * 80 + z * 32 + lcol);
                Bf[q * 2][0] = r0;     Bf[q * 2][1] = r2;
                Bf[q * 2 + 1][0] = r1; Bf[q * 2 + 1][1] = r3;
            }
            #pragma unroll
            for (int im = 0; im < 2; im++)
                #pragma unroll
                for (int in = 0; in < 8; in++)
                    mma_f8(acc[im][in], A[im], Bf[in]);
        }
    }

    const float SCL = 1.f / 65536.f;
    #pragma unroll
    for (int im = 0; im < 2; im++)
        #pragma unroll
        for (int in = 0; in < 8; in++)
            #pragma unroll
            for (int j = 0; j < 4; j++) acc[im][in][j] *= SCL;

    // InterRC in fp32
    const int sb = wm * 32 + g;
    const int fb = wn * 64 + 2 * tg;
    #pragma unroll
    for (int r = 0; r < R_N; r++) {
        float a00 = attsh[sb][r],      a01 = attsh[sb + 8][r];
        float a10 = attsh[sb + 16][r], a11 = attsh[sb + 24][r];
        #pragma unroll
        for (int in = 0; in < 8; in++) {
            float hv0 = h1sh[r][fb + in * 8];
            float hv1 = h1sh[r][fb + in * 8 + 1];
            acc[0][in][0] = fmaf(a00, hv0, acc[0][in][0]);
            acc[0][in][1] = fmaf(a00, hv1, acc[0][in][1]);
            acc[0][in][2] = fmaf(a01, hv0, acc[0][in][2]);
            acc[0][in][3] = fmaf(a01, hv1, acc[0][in][3]);
            acc[1][in][0] = fmaf(a10, hv0, acc[1][in][0]);
            acc[1][in][1] = fmaf(a10, hv1, acc[1][in][1]);
            acc[1][in][2] = fmaf(a11, hv0, acc[1][in][2]);
            acc[1][in][3] = fmaf(a11, hv1, acc[1][in][3]);
        }
    }
    // store u
    #pragma unroll
    for (int im = 0; im < 2; im++)
        #pragma unroll
        for (int hf = 0; hf < 2; hf++) {
            int s = s0 + wm * 32 + im * 16 + g + hf * 8;
            if (s < S_N) {
                float* up = &g_u[((size_t)h * S_N + s) * FD + fb];
                #pragma unroll
                for (int in = 0; in < 8; in++) {
                    float2 o = make_float2(acc[im][in][hf * 2], acc[im][in][hf * 2 + 1]);
                    *(float2*)(up + in * 8) = o;
                }
            }
        }
    // fused BN column partials
    __syncthreads();
    float* rs = (float*)sm6;
    float* rq = rs + 512;
    #pragma unroll
    for (int in = 0; in < 8; in++)
        #pragma unroll
        for (int half = 0; half < 2; half++) {
            float a0 = acc[0][in][half],     a1 = acc[0][in][2 + half];
            float a2 = acc[1][in][half],     a3 = acc[1][in][2 + half];
            float sm_ = a0 + a1 + a2 + a3;
            float sq_ = a0 * a0 + a1 * a1 + a2 * a2 + a3 * a3;
            #pragma unroll
            for (int o = 4; o <= 16; o <<= 1) {
                sm_ += __shfl_xor_sync(0xffffffffu, sm_, o);
                sq_ += __shfl_xor_sync(0xffffffffu, sq_, o);
            }
            if (lane < 4) {
                int f = wn * 64 + in * 8 + 2 * lane + half;
                rs[wm * 128 + f] = sm_;
                rq[wm * 128 + f] = sq_;
            }
        }
    __syncthreads();
    if (tid < 128) {
        float s4 = rs[tid] + rs[128 + tid] + rs[256 + tid] + rs[384 + tid];
        float q4 = rq[tid] + rq[128 + tid] + rq[256 + tid] + rq[384 + tid];
        g_upsum[tile * H_N * FD + h * FD + tid] = s4;
        g_upsq [tile * H_N * FD + h * FD + tid] = q4;
    }
}

// ---- K7b ----
__global__ void k7b_bnu(const float* __restrict__ g2, const float* __restrict__ b2) {
    int i = blockIdx.x * blockDim.x + threadIdx.x;
    if (i >= H_N * FD) return;
    float sm = 0.f, sq = 0.f;
    #pragma unroll 4
    for (int c = 0; c < 79; c++) {
        sm += g_upsum[c * H_N * FD + i];
        sq += g_upsq [c * H_N * FD + i];
    }
    float mean = sm / (float)S_N;
    float var = sq / (float)S_N - mean * mean;
    float al = g2[i] * rsqrtf(var + 1e-5f);
    g_alpha[i] = al;
    g_beta[i]  = b2[i] - mean * al;
}

// ---- K8 ----
__global__ void k8_out(const int* __restrict__ inter, const float* __restrict__ outW,
                       float* __restrict__ out) {
    int s = blockIdx.x * 8 + (threadIdx.x >> 5);
    int lane = threadIdx.x & 31;
    if (s >= S_N) return;
    float un[H_N][4];
    #pragma unroll
    for (int h = 0; h < H_N; h++)
        #pragma unroll
        for (int i = 0; i < 4; i++) {
            int f = lane + 32 * i;
            float x = g_u[((size_t)h * S_N + s) * FD + f];
            un[h][i] = lrelu(fmaf(x, g_alpha[h * FD + f], g_beta[h * FD + f]));
        }
    float hf = 0.f;
    #pragma unroll
    for (int h = 0; h < H_N; h++)
        for (int r = 0; r < R_N; r++) {
            float d = 0.f;
            #pragma unroll
            for (int i = 0; i < 4; i++) {
                int f = lane + 32 * i;
                d = fmaf(un[h][i], g_v[((h * R_N) + r) * FD + f], d);
            }
            #pragma unroll
            for (int o = 16; o > 0; o >>= 1) d += __shfl_xor_sync(0xffffffffu, d, o);
            float ho = elu(d);
            if (lane < C_N) hf = fmaf(ho, outW[(h * R_N + r) * C_N + lane], hf);
        }
    int adj = (lane < R_N) ? inter[s * R_N + lane] : 0;
    unsigned m = __ballot_sync(0xffffffffu, (lane < R_N) && adj > 0);
    int deg = __popc(m);
    float att = (deg > 0) ? (adj > 0 ? 1.f / (float)deg : 0.f) : (1.f / (float)R_N);
    float t = att * hf;
    t = elu(t);
    t = elu(t);
    float z = (lane < C_N) ? t : -3.4e38f;
    float mx = z;
    #pragma unroll
    for (int o = 8; o > 0; o >>= 1) mx = fmaxf(mx, __shfl_xor_sync(0xffffffffu, mx, o));
    float ex = (lane < C_N) ? expf(z - mx) : 0.f;
    float sm = ex;
    #pragma unroll
    for (int o = 8; o > 0; o >>= 1) sm += __shfl_xor_sync(0xffffffffu, sm, o);
    if (lane < C_N) out[s * C_N + lane] = (z - mx) - logf(sm);
}

// ---- launch ----
extern "C" void kernel_launch(void* const* d_in, const int* in_sizes, int n_in,
                              void* d_out, int out_size) {
    const int*   inter = (const int*)d_in[0];
    const int*   city  = (const int*)d_in[1];
    const int*   prov  = (const int*)d_in[2];
    const int*   src   = (const int*)d_in[3];
    const float* Sfeat = (const float*)d_in[4];
    const float* Rfeat = (const float*)d_in[5];
    const float* W1    = (const float*)d_in[6];
    const float* W2    = (const float*)d_in[7];
    const float* a     = (const float*)d_in[8];
    const float* bn1g  = (const float*)d_in[11];
    const float* bn1b  = (const float*)d_in[12];
    const float* bn2g  = (const float*)d_in[13];
    const float* bn2b  = (const float*)d_in[14];
    const float* outW  = (const float*)d_in[15];
    float* out = (float*)d_out;

    cudaFuncSetAttribute(k6_f8, cudaFuncAttributeMaxDynamicSharedMemorySize, K6_SMEM);

    k3_bits<<<B_N, 256>>>(city, prov, src);
    k3w_t8<<<dim3(SP / 32, B_N / 256), 256>>>();
    k1_h1<<<H_N * R_N, 128>>>(Rfeat, W1, a);
    k2_h2<<<dim3((S_N + 63) / 64, H_N), 256>>>(Sfeat, W2);   // profiled slot #4
    k3y8<<<256, 256>>>(src);
    k45_attv<<<dim3(158, H_N), 256>>>(inter, a);
    k5r<<<dim3(64, 2), 128>>>();
    k5b2<<<(H_N * FD + 127) / 128, 128>>>(bn1g, bn1b);
    k6_f8<<<dim3(79, H_N), 256, K6_SMEM>>>();
    k7b_bnu<<<(H_N * FD + 127) / 128, 128>>>(bn2g, bn2b);
    k8_out<<<(S_N + 7) / 8, 256>>>(inter, outW, out);
}

// round 10
// speedup vs baseline: 1.4687x; 1.0334x over previous
#include <cuda_runtime.h>
#include <cuda_bf16.h>
#include <cuda_fp8.h>
#include <math.h>
#include <stdint.h>

#define S_N 10000
#define R_N 16
#define FD 128
#define H_N 4
#define B_N 2048
#define C_N 16
#define NEG (-9e15f)
#define SW 313
#define SP 10112
#define NCH 158

__device__ float g_h1[H_N * R_N * FD];
__device__ float g_h1a[H_N * R_N];
__device__ float g_w2a[H_N * FD];                        // W2[h] @ a2[h]
__device__ float g_sg[(size_t)B_N * FD];                 // Sfeat[src]
__device__ unsigned g_cbits[B_N * SW];
__device__ unsigned g_pbits[B_N * SW];
__device__ float2 g_inv2[B_N];
__device__ unsigned char g_wbt8[(size_t)SP * B_N];       // (4096*W)^T [s][b] e4m3
__device__ unsigned char g_ybt8[(size_t)H_N * FD * B_N]; // (16*y)^T [h][f][b] e4m3
__device__ float g_att[H_N * S_N * R_N];
__device__ float g_vpart[NCH * H_N * R_N * FD];          // att^T @ Sfeat partials
__device__ float g_vsum[2 * H_N * R_N * FD];
__device__ float g_vraw[H_N * R_N * FD];
__device__ float g_v[H_N * R_N * FD];
__device__ float g_u[(size_t)H_N * S_N * FD];
__device__ float g_upsum[79 * H_N * FD];
__device__ float g_upsq[79 * H_N * FD];
__device__ float g_alpha[H_N * FD];
__device__ float g_beta[H_N * FD];

__device__ __forceinline__ float lrelu(float x) { return x > 0.f ? x : 0.2f * x; }
__device__ __forceinline__ float elu(float x)   { return x > 0.f ? x : expm1f(x); }
__device__ __forceinline__ unsigned su(const void* p) {
    return (unsigned)__cvta_generic_to_shared(p);
}
__device__ __forceinline__ void ldmx4(unsigned& r0, unsigned& r1, unsigned& r2,
                                      unsigned& r3, unsigned addr) {
    asm volatile("ldmatrix.sync.aligned.m8n8.x4.shared.b16 {%0,%1,%2,%3},[%4];"
                 : "=r"(r0), "=r"(r1), "=r"(r2), "=r"(r3) : "r"(addr));
}
__device__ __forceinline__ void mma_f8(float c[4], const unsigned a[4], const unsigned b[2]) {
    asm volatile(
        "mma.sync.aligned.m16n8k32.row.col.f32.e4m3.e4m3.f32 "
        "{%0,%1,%2,%3},{%4,%5,%6,%7},{%8,%9},{%0,%1,%2,%3};"
        : "+f"(c[0]), "+f"(c[1]), "+f"(c[2]), "+f"(c[3])
        : "r"(a[0]), "r"(a[1]), "r"(a[2]), "r"(a[3]), "r"(b[0]), "r"(b[1]));
}
__device__ __forceinline__ unsigned short f8pack(float lo, float hi) {
    unsigned short p;
    asm("cvt.rn.satfinite.e4m3x2.f32 %0, %1, %2;" : "=h"(p) : "f"(hi), "f"(lo));
    return p;
}
#define CP16(d, s) asm volatile("cp.async.cg.shared.global [%0],[%1],16;" ::"r"(d), "l"(s))
#define CPCOMMIT   asm volatile("cp.async.commit_group;")

// ---- K3: bitpack adjacency + degrees ----
__global__ void k3_bits(const int* __restrict__ city, const int* __restrict__ prov,
                        const int* __restrict__ src) {
    int b = blockIdx.x;
    int n = src[b];
    const int* crow = city + (size_t)n * S_N;
    const int* prow = prov + (size_t)n * S_N;
    int lane = threadIdx.x & 31, wid = threadIdx.x >> 5;
    int degc = 0, degp = 0;
    for (int w = wid; w < SW; w += 8) {
        int s = w * 32 + lane;
        bool inb = s < S_N;
        int cv = inb ? crow[s] : 0;
        int pv = inb ? prow[s] : 0;
        unsigned cm = __ballot_sync(0xffffffffu, cv > 0);
        unsigned pm = __ballot_sync(0xffffffffu, pv > 0);
        if (lane == 0) {
            g_cbits[b * SW + w] = cm;
            g_pbits[b * SW + w] = pm;
            degc += __popc(cm);
            degp += __popc(pm);
        }
    }
    __shared__ int sdc[8], sdp[8];
    if (lane == 0) { sdc[wid] = degc; sdp[wid] = degp; }
    __syncthreads();
    if (threadIdx.x == 0) {
        int dc = 0, dp = 0;
        for (int i = 0; i < 8; i++) { dc += sdc[i]; dp += sdp[i]; }
        g_inv2[b] = make_float2(dc > 0 ? 1.f / (float)dc : 0.f,
                                dp > 0 ? 1.f / (float)dp : 0.f);
    }
}

// ---- KW2A: w2a[h][k] = sum_f W2[h][k][f] * a2[h][f] ----
__global__ void kw2a(const float* __restrict__ W2, const float* __restrict__ a) {
    int h = blockIdx.x, k = threadIdx.x;
    const float* w  = W2 + (size_t)h * FD * FD + (size_t)k * FD;
    const float* a2 = a + h * 2 * FD + FD;
    float acc = 0.f;
    #pragma unroll 8
    for (int f = 0; f < FD; f++) acc = fmaf(w[f], a2[f], acc);
    g_w2a[h * FD + k] = acc;
}

// ---- K1: h1 = Rfeat @ W1[h], h1a ----
__global__ void k1_h1(const float* __restrict__ Rfeat, const float* __restrict__ W1,
                      const float* __restrict__ a) {
    int h = blockIdx.x / R_N, r = blockIdx.x % R_N, f = threadIdx.x;
    const float* w  = W1 + (size_t)h * FD * FD;
    const float* rf = Rfeat + r * FD;
    float acc = 0.f;
    #pragma unroll 8
    for (int k = 0; k < FD; k++) acc = fmaf(rf[k], w[k * FD + f], acc);
    g_h1[(h * R_N + r) * FD + f] = acc;
    __shared__ float sh[128];
    sh[f] = acc * a[h * 2 * FD + f];
    __syncthreads();
    for (int st = 64; st > 0; st >>= 1) {
        if (f < st) sh[f] += sh[f + st];
        __syncthreads();
    }
    if (f == 0) g_h1a[h * R_N + r] = sh[0];
}

// ---- K45: attention (via Sfeat . w2a) + M partials = att^T @ Sfeat ----
// profiled slot #4
__global__ __launch_bounds__(256) void k45_attv(const int* __restrict__ inter,
                                                const float* __restrict__ Sfeat) {
    const int h = blockIdx.y, tile = blockIdx.x, s0 = tile * 64;
    const int tid = threadIdx.x, lane = tid & 31, w = tid >> 5;
    __shared__ float attS[64][17];
    __shared__ float red[R_N * 128];
    float wv[4];
    #pragma unroll
    for (int i = 0; i < 4; i++) wv[i] = g_w2a[h * FD + lane + 32 * i];
    #pragma unroll
    for (int it = 0; it < 8; it++) {
        int sl = w * 8 + it;
        int s = s0 + sl;
        if (s < S_N) {
            const float* row = &Sfeat[(size_t)s * FD];
            float d = 0.f;
            #pragma unroll
            for (int i = 0; i < 4; i++) d = fmaf(row[lane + 32 * i], wv[i], d);
            #pragma unroll
            for (int o = 16; o > 0; o >>= 1) d += __shfl_xor_sync(0xffffffffu, d, o);
            float z = NEG;
            if (lane < R_N && inter[s * R_N + lane] > 0)
                z = lrelu(d + g_h1a[h * R_N + lane]);
            float mx = z;
            #pragma unroll
            for (int o = 8; o > 0; o >>= 1) mx = fmaxf(mx, __shfl_xor_sync(0xffffffffu, mx, o));
            float ex = (lane < R_N) ? expf(z - mx) : 0.f;
            float sm = ex;
            #pragma unroll
            for (int o = 8; o > 0; o >>= 1) sm += __shfl_xor_sync(0xffffffffu, sm, o);
            if (lane < R_N) {
                float av = ex / sm;
                attS[sl][lane] = av;
                g_att[((h * S_N) + s) * R_N + lane] = av;
            }
        } else if (lane < R_N) {
            attS[sl][lane] = 0.f;
        }
    }
    __syncthreads();
    const int f = tid & 127, half = tid >> 7;
    float acc[R_N];
    #pragma unroll
    for (int r = 0; r < R_N; r++) acc[r] = 0.f;
    const int base = half * 32;
    for (int si = 0; si < 32; si++) {
        int s = s0 + base + si;
        if (s >= S_N) break;
        float v = Sfeat[(size_t)s * FD + f];
        #pragma unroll
        for (int r = 0; r < R_N; r++) acc[r] = fmaf(attS[base + si][r], v, acc[r]);
    }
    if (half == 1) {
        #pragma unroll
        for (int r = 0; r < R_N; r++) red[r * 128 + f] = acc[r];
    }
    __syncthreads();
    if (half == 0) {
        #pragma unroll
        for (int r = 0; r < R_N; r++)
            g_vpart[((tile * H_N * R_N) + h * R_N + r) * FD + f] =
                acc[r] + red[r * 128 + f];
    }
}

// ---- KSG: gather Sfeat[src] ----
__global__ void ksg(const float* __restrict__ Sfeat, const int* __restrict__ src) {
    int b = blockIdx.x, f = threadIdx.x;
    g_sg[(size_t)b * FD + f] = Sfeat[(size_t)src[b] * FD + f];
}

// ---- KY: y^T fp8 = (16 * Sg @ W2[h])^T ----
__global__ __launch_bounds__(256) void kY(const float* __restrict__ W2) {
    const int h = blockIdx.y;
    const int b0 = blockIdx.x * 64;
    const int tid = threadIdx.x;
    const int tx = tid & 31;     // f = 4*tx
    const int ty = tid >> 5;     // b group of 8
    __shared__ float sf[FD][68];
    for (int i = tid; i < 64 * FD; i += 256) {
        int bl = i >> 7, k = i & 127;
        sf[k][bl] = g_sg[(size_t)(b0 + bl) * FD + k];
    }
    __syncthreads();
    float acc[8][4];
    #pragma unroll
    for (int i = 0; i < 8; i++)
        #pragma unroll
        for (int j = 0; j < 4; j++) acc[i][j] = 0.f;
    const float4* w4 = (const float4*)(W2 + (size_t)h * FD * FD);
    #pragma unroll 4
    for (int k = 0; k < FD; k++) {
        float4 wq = w4[k * 32 + tx];
        float4 sa = *(const float4*)&sf[k][ty * 8];
        float4 sb = *(const float4*)&sf[k][ty * 8 + 4];
        float sv[8] = {sa.x, sa.y, sa.z, sa.w, sb.x, sb.y, sb.z, sb.w};
        #pragma unroll
        for (int i = 0; i < 8; i++) {
            acc[i][0] = fmaf(sv[i], wq.x, acc[i][0]);
            acc[i][1] = fmaf(sv[i], wq.y, acc[i][1]);
            acc[i][2] = fmaf(sv[i], wq.z, acc[i][2]);
            acc[i][3] = fmaf(sv[i], wq.w, acc[i][3]);
        }
    }
    __syncthreads();
    unsigned char (*tb)[64] = (unsigned char(*)[64])sf;  // reuse smem (8KB)
    #pragma unroll
    for (int i = 0; i < 8; i++)
        #pragma unroll
        for (int j = 0; j < 4; j++)
            tb[tx * 4 + j][ty * 8 + i] = (unsigned char)f8pack(acc[i][j] * 16.f, 0.f);
    __syncthreads();
    for (int u = tid; u < 512; u += 256) {
        int f = u >> 2, part = u & 3;
        *(uint4*)&g_ybt8[((size_t)h * FD + f) * B_N + b0 + part * 16] =
            *(const uint4*)&tb[f][part * 16];
    }
}

// ---- K3w: (4096*W)^T[s][b] e4m3 via smem transpose ----
__global__ __launch_bounds__(256) void k3w_t8() {
    __shared__ __align__(16) unsigned char st[32][256];
    const int s0 = blockIdx.x * 32, b0 = blockIdx.y * 256;
    const int t = threadIdx.x;
    const int b = b0 + t;
    unsigned cw = 0, pw = 0;
    float2 iv = make_float2(0.f, 0.f);
    if (s0 < S_N) {
        cw = g_cbits[(size_t)b * SW + (s0 >> 5)];
        pw = g_pbits[(size_t)b * SW + (s0 >> 5)];
        iv = g_inv2[b];
    }
    float ic = iv.x * 4096.f, ip = iv.y * 4096.f;
    #pragma unroll
    for (int sl = 0; sl < 32; sl++) {
        float v = ((cw >> sl) & 1u) ? ic : 0.f;
        if ((pw >> sl) & 1u) v += ip;
        st[sl][t] = (unsigned char)f8pack(v, 0.f);
    }
    __syncthreads();
    #pragma unroll
    for (int j = 0; j < 2; j++) {
        int idx = t + j * 256;
        int row = idx >> 4, sg = idx & 15;
        uint4 val = *(const uint4*)&st[row][sg * 16];
        *(uint4*)&g_wbt8[(size_t)(s0 + row) * B_N + b0 + sg * 16] = val;
    }
}

// ---- K5r: reduce vpart chunks ----
__global__ void k5r() {
    int h = blockIdx.x >> 4, r = blockIdx.x & 15;
    int part = blockIdx.y, f = threadIdx.x;
    int c0 = part * 79;
    float t = 0.f;
    #pragma unroll 4
    for (int c = 0; c < 79; c++)
        t += g_vpart[(((c0 + c) * H_N * R_N) + h * R_N + r) * FD + f];
    g_vsum[((part * H_N + h) * R_N + r) * FD + f] = t;
}

// ---- K5m: vraw = M @ W2[h] ----
__global__ void k5m(const float* __restrict__ W2) {
    int h = blockIdx.x >> 4, r = blockIdx.x & 15;
    int f = threadIdx.x;
    __shared__ float M[128];
    M[f] = g_vsum[((0 * H_N + h) * R_N + r) * FD + f]
         + g_vsum[((1 * H_N + h) * R_N + r) * FD + f];
    __syncthreads();
    const float* w = W2 + (size_t)h * FD * FD;
    float acc = 0.f;
    #pragma unroll 8
    for (int k = 0; k < FD; k++) acc = fmaf(M[k], w[k * FD + f], acc);
    g_vraw[(h * R_N + r) * FD + f] = acc;
}

// ---- K5b2: BN over R + lrelu -> g_v ----
__global__ void k5b2(const float* __restrict__ g1, const float* __restrict__ b1) {
    int i = blockIdx.x * blockDim.x + threadIdx.x;
    if (i >= H_N * FD) return;
    int h = i / FD, f = i % FD;
    float x[R_N];
    float m = 0.f;
    #pragma unroll
    for (int r = 0; r < R_N; r++) {
        float t = g_vraw[(h * R_N + r) * FD + f];
        x[r] = t;
        m += t;
    }
    m *= (1.f / R_N);
    float var = 0.f;
    #pragma unroll
    for (int r = 0; r < R_N; r++) { float d = x[r] - m; var = fmaf(d, d, var); }
    var *= (1.f / R_N);
    float inv = rsqrtf(var + 1e-5f);
    float gg = g1[i], bb = b1[i];
    #pragma unroll
    for (int r = 0; r < R_N; r++)
        g_v[((h * R_N) + r) * FD + f] = lrelu((x[r] - m) * inv * gg + bb);
}

// ---- K6: fp8 GEMM, 4-stage pipeline + fp32 InterRC + BN partials ----
#define K6_SMEM 98816
__device__ __forceinline__ void k6_stage(char* sm, int c, int h, int s0, int tid) {
    int st = c & 3;
    uint32_t ab = su(sm) + st * 10240;
    uint32_t bb = su(sm) + 40960 + st * 10240;
    #pragma unroll
    for (int j = 0; j < 2; j++) {
        int idx = tid + j * 256;
        int row = idx >> 2, sg = idx & 3;
        CP16(ab + row * 80 + sg * 16, &g_wbt8[(size_t)(s0 + row) * B_N + c * 64 + sg * 16]);
        CP16(bb + row * 80 + sg * 16, &g_ybt8[((size_t)h * FD + row) * B_N + c * 64 + sg * 16]);
    }
    CPCOMMIT;
}

__global__ __launch_bounds__(256, 2) void k6_f8() {
    extern __shared__ __align__(16) char sm6[];
    float (*attsh)[17] = (float(*)[17])(sm6 + 81920);
    float (*h1sh)[128] = (float(*)[128])(sm6 + 90624);

    const int h = blockIdx.y, tile = blockIdx.x, s0 = tile * 128;
    const int tid = threadIdx.x, lane = tid & 31, w = tid >> 5;
    const int wm = w >> 1, wn = w & 1;
    const int g = lane >> 2, tg = lane & 3;

    for (int i = tid; i < 128 * R_N; i += 256) {
        int sl = i >> 4, r = i & 15;
        int s = s0 + sl;
        attsh[sl][r] = (s < S_N) ? g_att[((h * S_N) + s) * R_N + r] : 0.f;
    }
    for (int i = tid; i < R_N * FD; i += 256)
        h1sh[i >> 7][i & 127] = g_h1[h * R_N * FD + i];

    float acc[2][8][4] = {};
    k6_stage(sm6, 0, h, s0, tid);
    k6_stage(sm6, 1, h, s0, tid);
    k6_stage(sm6, 2, h, s0, tid);

    const int lrow = lane & 15;
    const int lcol = (lane >> 4) * 16;

    for (int c = 0; c < 32; c++) {
        if (c < 30)      { asm volatile("cp.async.wait_group 2;"); }
        else if (c == 30){ asm volatile("cp.async.wait_group 1;"); }
        else             { asm volatile("cp.async.wait_group 0;"); }
        __syncthreads();
        if (c + 3 < 32) k6_stage(sm6, c + 3, h, s0, tid);
        const int buf = c & 3;
        uint32_t abase = su(sm6) + buf * 10240;
        uint32_t bbase = su(sm6) + 40960 + buf * 10240;
        #pragma unroll
        for (int z = 0; z < 2; z++) {
            unsigned A[2][4];
            #pragma unroll
            for (int im = 0; im < 2; im++)
                ldmx4(A[im][0], A[im][1], A[im][2], A[im][3],
                      abase + (wm * 32 + im * 16 + lrow) * 80 + z * 32 + lcol);
            unsigned Bf[8][2];
            #pragma unroll
            for (int q = 0; q < 4; q++) {
                unsigned r0, r1, r2, r3;
                ldmx4(r0, r1, r2, r3,
                      bbase + (wn * 64 + q * 16 + lrow) * 80 + z * 32 + lcol);
                Bf[q * 2][0] = r0;     Bf[q * 2][1] = r2;
                Bf[q * 2 + 1][0] = r1; Bf[q * 2 + 1][1] = r3;
            }
            #pragma unroll
            for (int im = 0; im < 2; im++)
                #pragma unroll
                for (int in = 0; in < 8; in++)
                    mma_f8(acc[im][in], A[im], Bf[in]);
        }
    }

    const float SCL = 1.f / 65536.f;
    #pragma unroll
    for (int im = 0; im < 2; im++)
        #pragma unroll
        for (int in = 0; in < 8; in++)
            #pragma unroll
            for (int j = 0; j < 4; j++) acc[im][in][j] *= SCL;

    const int sb = wm * 32 + g;
    const int fb = wn * 64 + 2 * tg;
    #pragma unroll
    for (int r = 0; r < R_N; r++) {
        float a00 = attsh[sb][r],      a01 = attsh[sb + 8][r];
        float a10 = attsh[sb + 16][r], a11 = attsh[sb + 24][r];
        #pragma unroll
        for (int in = 0; in < 8; in++) {
            float hv0 = h1sh[r][fb + in * 8];
            float hv1 = h1sh[r][fb + in * 8 + 1];
            acc[0][in][0] = fmaf(a00, hv0, acc[0][in][0]);
            acc[0][in][1] = fmaf(a00, hv1, acc[0][in][1]);
            acc[0][in][2] = fmaf(a01, hv0, acc[0][in][2]);
            acc[0][in][3] = fmaf(a01, hv1, acc[0][in][3]);
            acc[1][in][0] = fmaf(a10, hv0, acc[1][in][0]);
            acc[1][in][1] = fmaf(a10, hv1, acc[1][in][1]);
            acc[1][in][2] = fmaf(a11, hv0, acc[1][in][2]);
            acc[1][in][3] = fmaf(a11, hv1, acc[1][in][3]);
        }
    }
    #pragma unroll
    for (int im = 0; im < 2; im++)
        #pragma unroll
        for (int hf = 0; hf < 2; hf++) {
            int s = s0 + wm * 32 + im * 16 + g + hf * 8;
            if (s < S_N) {
                float* up = &g_u[((size_t)h * S_N + s) * FD + fb];
                #pragma unroll
                for (int in = 0; in < 8; in++) {
                    float2 o = make_float2(acc[im][in][hf * 2], acc[im][in][hf * 2 + 1]);
                    *(float2*)(up + in * 8) = o;
                }
            }
        }
    __syncthreads();
    float* rs = (float*)sm6;
    float* rq = rs + 512;
    #pragma unroll
    for (int in = 0; in < 8; in++)
        #pragma unroll
        for (int half = 0; half < 2; half++) {
            float a0 = acc[0][in][half],     a1 = acc[0][in][2 + half];
            float a2 = acc[1][in][half],     a3 = acc[1][in][2 + half];
            float sm_ = a0 + a1 + a2 + a3;
            float sq_ = a0 * a0 + a1 * a1 + a2 * a2 + a3 * a3;
            #pragma unroll
            for (int o = 4; o <= 16; o <<= 1) {
                sm_ += __shfl_xor_sync(0xffffffffu, sm_, o);
                sq_ += __shfl_xor_sync(0xffffffffu, sq_, o);
            }
            if (lane < 4) {
                int f = wn * 64 + in * 8 + 2 * lane + half;
                rs[wm * 128 + f] = sm_;
                rq[wm * 128 + f] = sq_;
            }
        }
    __syncthreads();
    if (tid < 128) {
        float s4 = rs[tid] + rs[128 + tid] + rs[256 + tid] + rs[384 + tid];
        float q4 = rq[tid] + rq[128 + tid] + rq[256 + tid] + rq[384 + tid];
        g_upsum[tile * H_N * FD + h * FD + tid] = s4;
        g_upsq [tile * H_N * FD + h * FD + tid] = q4;
    }
}

// ---- K7b ----
__global__ void k7b_bnu(const float* __restrict__ g2, const float* __restrict__ b2) {
    int i = blockIdx.x * blockDim.x + threadIdx.x;
    if (i >= H_N * FD) return;
    float sm = 0.f, sq = 0.f;
    #pragma unroll 4
    for (int c = 0; c < 79; c++) {
        sm += g_upsum[c * H_N * FD + i];
        sq += g_upsq [c * H_N * FD + i];
    }
    float mean = sm / (float)S_N;
    float var = sq / (float)S_N - mean * mean;
    float al = g2[i] * rsqrtf(var + 1e-5f);
    g_alpha[i] = al;
    g_beta[i]  = b2[i] - mean * al;
}

// ---- K8 ----
__global__ void k8_out(const int* __restrict__ inter, const float* __restrict__ outW,
                       float* __restrict__ out) {
    int s = blockIdx.x * 8 + (threadIdx.x >> 5);
    int lane = threadIdx.x & 31;
    if (s >= S_N) return;
    float un[H_N][4];
    #pragma unroll
    for (int h = 0; h < H_N; h++)
        #pragma unroll
        for (int i = 0; i < 4; i++) {
            int f = lane + 32 * i;
            float x = g_u[((size_t)h * S_N + s) * FD + f];
            un[h][i] = lrelu(fmaf(x, g_alpha[h * FD + f], g_beta[h * FD + f]));
        }
    float hf = 0.f;
    #pragma unroll
    for (int h = 0; h < H_N; h++)
        for (int r = 0; r < R_N; r++) {
            float d = 0.f;
            #pragma unroll
            for (int i = 0; i < 4; i++) {
                int f = lane + 32 * i;
                d = fmaf(un[h][i], g_v[((h * R_N) + r) * FD + f], d);
            }
            #pragma unroll
            for (int o = 16; o > 0; o >>= 1) d += __shfl_xor_sync(0xffffffffu, d, o);
            float ho = elu(d);
            if (lane < C_N) hf = fmaf(ho, outW[(h * R_N + r) * C_N + lane], hf);
        }
    int adj = (lane < R_N) ? inter[s * R_N + lane] : 0;
    unsigned m = __ballot_sync(0xffffffffu, (lane < R_N) && adj > 0);
    int deg = __popc(m);
    float att = (deg > 0) ? (adj > 0 ? 1.f / (float)deg : 0.f) : (1.f / (float)R_N);
    float t = att * hf;
    t = elu(t);
    t = elu(t);
    float z = (lane < C_N) ? t : -3.4e38f;
    float mx = z;
    #pragma unroll
    for (int o = 8; o > 0; o >>= 1) mx = fmaxf(mx, __shfl_xor_sync(0xffffffffu, mx, o));
    float ex = (lane < C_N) ? expf(z - mx) : 0.f;
    float sm = ex;
    #pragma unroll
    for (int o = 8; o > 0; o >>= 1) sm += __shfl_xor_sync(0xffffffffu, sm, o);
    if (lane < C_N) out[s * C_N + lane] = (z - mx) - logf(sm);
}

// ---- launch ----
extern "C" void kernel_launch(void* const* d_in, const int* in_sizes, int n_in,
                              void* d_out, int out_size) {
    const int*   inter = (const int*)d_in[0];
    const int*   city  = (const int*)d_in[1];
    const int*   prov  = (const int*)d_in[2];
    const int*   src   = (const int*)d_in[3];
    const float* Sfeat = (const float*)d_in[4];
    const float* Rfeat = (const float*)d_in[5];
    const float* W1    = (const float*)d_in[6];
    const float* W2    = (const float*)d_in[7];
    const float* a     = (const float*)d_in[8];
    const float* bn1g  = (const float*)d_in[11];
    const float* bn1b  = (const float*)d_in[12];
    const float* bn2g  = (const float*)d_in[13];
    const float* bn2b  = (const float*)d_in[14];
    const float* outW  = (const float*)d_in[15];
    float* out = (float*)d_out;

    cudaFuncSetAttribute(k6_f8, cudaFuncAttributeMaxDynamicSharedMemorySize, K6_SMEM);

    k3_bits<<<B_N, 256>>>(city, prov, src);
    kw2a<<<H_N, 128>>>(W2, a);
    k1_h1<<<H_N * R_N, 128>>>(Rfeat, W1, a);
    k45_attv<<<dim3(158, H_N), 256>>>(inter, Sfeat);   // profiled slot #4
    ksg<<<B_N, 128>>>(Sfeat, src);
    kY<<<dim3(B_N / 64, H_N), 256>>>(W2);
    k3w_t8<<<dim3(SP / 32, B_N / 256), 256>>>();
    k5r<<<dim3(64, 2), 128>>>();
    k5m<<<H_N * R_N, 128>>>(W2);
    k5b2<<<(H_N * FD + 127) / 128, 128>>>(bn1g, bn1b);
    k6_f8<<<dim3(79, H_N), 256, K6_SMEM>>>();
    k7b_bnu<<<(H_N * FD + 127) / 128, 128>>>(bn2g, bn2b);
    k8_out<<<(S_N + 7) / 8, 256>>>(inter, outW, out);
}

// round 11
// speedup vs baseline: 1.8037x; 1.2281x over previous
#include <cuda_runtime.h>
#include <cuda_bf16.h>
#include <cuda_fp8.h>
#include <math.h>
#include <stdint.h>

#define S_N 10000
#define R_N 16
#define FD 128
#define H_N 4
#define B_N 2048
#define C_N 16
#define NEG (-9e15f)
#define SW 313
#define SP 10112
#define NCH 158

__device__ float g_h1[H_N * R_N * FD];
__device__ float g_h1a[H_N * R_N];
__device__ float g_w2a[H_N * FD];
__device__ unsigned g_cbits[B_N * SW];
__device__ unsigned g_pbits[B_N * SW];
__device__ float2 g_inv2[B_N];
__device__ unsigned char g_wbt8[(size_t)SP * B_N];   // (4096*W)^T [s][b] e4m3
__device__ unsigned char g_sgt8[(size_t)FD * B_N];   // (32*Sfeat[src])^T [f][b] e4m3
__device__ __nv_bfloat16 g_z[(size_t)SP * FD];       // Z = W^T @ Sg (true scale)
__device__ float g_att[H_N * S_N * R_N];
__device__ float g_vpart[NCH * H_N * R_N * FD];
__device__ float g_vsum[2 * H_N * R_N * FD];
__device__ float g_vraw[H_N * R_N * FD];
__device__ float g_v[H_N * R_N * FD];
__device__ float g_u[(size_t)H_N * S_N * FD];
__device__ float g_upsum[79 * H_N * FD];
__device__ float g_upsq[79 * H_N * FD];
__device__ float g_alpha[H_N * FD];
__device__ float g_beta[H_N * FD];

__device__ __forceinline__ float lrelu(float x) { return x > 0.f ? x : 0.2f * x; }
__device__ __forceinline__ float elu(float x)   { return x > 0.f ? x : expm1f(x); }
__device__ __forceinline__ unsigned su(const void* p) {
    return (unsigned)__cvta_generic_to_shared(p);
}
__device__ __forceinline__ void ldmx4(unsigned& r0, unsigned& r1, unsigned& r2,
                                      unsigned& r3, unsigned addr) {
    asm volatile("ldmatrix.sync.aligned.m8n8.x4.shared.b16 {%0,%1,%2,%3},[%4];"
                 : "=r"(r0), "=r"(r1), "=r"(r2), "=r"(r3) : "r"(addr));
}
__device__ __forceinline__ void ldmx4t(unsigned& r0, unsigned& r1, unsigned& r2,
                                       unsigned& r3, unsigned addr) {
    asm volatile("ldmatrix.sync.aligned.m8n8.x4.trans.shared.b16 {%0,%1,%2,%3},[%4];"
                 : "=r"(r0), "=r"(r1), "=r"(r2), "=r"(r3) : "r"(addr));
}
__device__ __forceinline__ void mma_f8(float c[4], const unsigned a[4], const unsigned b[2]) {
    asm volatile(
        "mma.sync.aligned.m16n8k32.row.col.f32.e4m3.e4m3.f32 "
        "{%0,%1,%2,%3},{%4,%5,%6,%7},{%8,%9},{%0,%1,%2,%3};"
        : "+f"(c[0]), "+f"(c[1]), "+f"(c[2]), "+f"(c[3])
        : "r"(a[0]), "r"(a[1]), "r"(a[2]), "r"(a[3]), "r"(b[0]), "r"(b[1]));
}
__device__ __forceinline__ void mma_bf16(float c[4], const unsigned a[4], const unsigned b[2]) {
    asm volatile(
        "mma.sync.aligned.m16n8k16.row.col.f32.bf16.bf16.f32 "
        "{%0,%1,%2,%3},{%4,%5,%6,%7},{%8,%9},{%0,%1,%2,%3};"
        : "+f"(c[0]), "+f"(c[1]), "+f"(c[2]), "+f"(c[3])
        : "r"(a[0]), "r"(a[1]), "r"(a[2]), "r"(a[3]), "r"(b[0]), "r"(b[1]));
}
__device__ __forceinline__ unsigned short f8pack(float lo, float hi) {
    unsigned short p;
    asm("cvt.rn.satfinite.e4m3x2.f32 %0, %1, %2;" : "=h"(p) : "f"(hi), "f"(lo));
    return p;
}
#define CP16(d, s) asm volatile("cp.async.cg.shared.global [%0],[%1],16;" ::"r"(d), "l"(s))
#define CPCOMMIT   asm volatile("cp.async.commit_group;")

// ---- K3: bitpack adjacency + degrees ----
__global__ void k3_bits(const int* __restrict__ city, const int* __restrict__ prov,
                        const int* __restrict__ src) {
    int b = blockIdx.x;
    int n = src[b];
    const int* crow = city + (size_t)n * S_N;
    const int* prow = prov + (size_t)n * S_N;
    int lane = threadIdx.x & 31, wid = threadIdx.x >> 5;
    int degc = 0, degp = 0;
    for (int w = wid; w < SW; w += 8) {
        int s = w * 32 + lane;
        bool inb = s < S_N;
        int cv = inb ? crow[s] : 0;
        int pv = inb ? prow[s] : 0;
        unsigned cm = __ballot_sync(0xffffffffu, cv > 0);
        unsigned pm = __ballot_sync(0xffffffffu, pv > 0);
        if (lane == 0) {
            g_cbits[b * SW + w] = cm;
            g_pbits[b * SW + w] = pm;
            degc += __popc(cm);
            degp += __popc(pm);
        }
    }
    __shared__ int sdc[8], sdp[8];
    if (lane == 0) { sdc[wid] = degc; sdp[wid] = degp; }
    __syncthreads();
    if (threadIdx.x == 0) {
        int dc = 0, dp = 0;
        for (int i = 0; i < 8; i++) { dc += sdc[i]; dp += sdp[i]; }
        g_inv2[b] = make_float2(dc > 0 ? 1.f / (float)dc : 0.f,
                                dp > 0 ? 1.f / (float)dp : 0.f);
    }
}

// ---- K3w: (4096*W)^T[s][b] e4m3 via smem transpose ----
__global__ __launch_bounds__(256) void k3w_t8() {
    __shared__ __align__(16) unsigned char st[32][256];
    const int s0 = blockIdx.x * 32, b0 = blockIdx.y * 256;
    const int t = threadIdx.x;
    const int b = b0 + t;
    unsigned cw = 0, pw = 0;
    float2 iv = make_float2(0.f, 0.f);
    if (s0 < S_N) {
        cw = g_cbits[(size_t)b * SW + (s0 >> 5)];
        pw = g_pbits[(size_t)b * SW + (s0 >> 5)];
        iv = g_inv2[b];
    }
    float ic = iv.x * 4096.f, ip = iv.y * 4096.f;
    #pragma unroll
    for (int sl = 0; sl < 32; sl++) {
        float v = ((cw >> sl) & 1u) ? ic : 0.f;
        if ((pw >> sl) & 1u) v += ip;
        st[sl][t] = (unsigned char)f8pack(v, 0.f);
    }
    __syncthreads();
    #pragma unroll
    for (int j = 0; j < 2; j++) {
        int idx = t + j * 256;
        int row = idx >> 4, sg = idx & 15;
        uint4 val = *(const uint4*)&st[row][sg * 16];
        *(uint4*)&g_wbt8[(size_t)(s0 + row) * B_N + b0 + sg * 16] = val;
    }
}

// ---- KSGT8: (32*Sfeat[src])^T [f][b] e4m3 ----
__global__ void ksgT8(const float* __restrict__ Sfeat, const int* __restrict__ src) {
    int idx = blockIdx.x * 256 + threadIdx.x;   // 64 blocks x 256 = 16384
    int f = idx & 127;
    int bg = idx >> 7;                          // 0..127
    __align__(16) unsigned short o8[8];
    #pragma unroll
    for (int j = 0; j < 8; j++) {
        int bb = bg * 16 + 2 * j;
        float v0 = Sfeat[(size_t)src[bb] * FD + f] * 32.f;
        float v1 = Sfeat[(size_t)src[bb + 1] * FD + f] * 32.f;
        o8[j] = f8pack(v0, v1);
    }
    *(uint4*)&g_sgt8[(size_t)f * B_N + bg * 16] = *(const uint4*)o8;
}

// ---- KZ: Z[SP x 128] = W^T @ Sg (fp8 mma, K=2048), profiled slot #4 ----
// smem: A 4x5120 @0 | B 4x10240 @20480  => 61440
#define KZ_SMEM 61440
__device__ __forceinline__ void kz_stage(char* sm, int c, int s0, int tid) {
    int st = c & 3;
    uint32_t ab = su(sm) + st * 5120;
    uint32_t bb = su(sm) + 20480 + st * 10240;
    {
        int row = tid >> 2, sg = tid & 3;
        CP16(ab + row * 80 + sg * 16, &g_wbt8[(size_t)(s0 + row) * B_N + c * 64 + sg * 16]);
    }
    #pragma unroll
    for (int j = 0; j < 2; j++) {
        int idx = tid + j * 256;
        int row = idx >> 2, sg = idx & 3;
        CP16(bb + row * 80 + sg * 16, &g_sgt8[(size_t)row * B_N + c * 64 + sg * 16]);
    }
    CPCOMMIT;
}

__global__ __launch_bounds__(256, 2) void kZ() {
    extern __shared__ __align__(16) char smz[];
    const int tile = blockIdx.x, s0 = tile * 64;
    const int tid = threadIdx.x, lane = tid & 31, w = tid >> 5;
    const int wm = w >> 1, wn = w & 1;       // 4m x 2n; warp = 16s x 64f
    const int g = lane >> 2, tg = lane & 3;
    float acc[8][4] = {};
    kz_stage(smz, 0, s0, tid);
    kz_stage(smz, 1, s0, tid);
    kz_stage(smz, 2, s0, tid);
    const int lrow = lane & 15, lcol = (lane >> 4) * 16;
    for (int c = 0; c < 32; c++) {
        if (c < 30)      { asm volatile("cp.async.wait_group 2;"); }
        else if (c == 30){ asm volatile("cp.async.wait_group 1;"); }
        else             { asm volatile("cp.async.wait_group 0;"); }
        __syncthreads();
        if (c + 3 < 32) kz_stage(smz, c + 3, s0, tid);
        int st = c & 3;
        uint32_t abase = su(smz) + st * 5120;
        uint32_t bbase = su(smz) + 20480 + st * 10240;
        #pragma unroll
        for (int z = 0; z < 2; z++) {
            unsigned A[4];
            ldmx4(A[0], A[1], A[2], A[3],
                  abase + (wm * 16 + lrow) * 80 + z * 32 + lcol);
            unsigned Bf[8][2];
            #pragma unroll
            for (int q = 0; q < 4; q++) {
                unsigned r0, r1, r2, r3;
                ldmx4(r0, r1, r2, r3,
                      bbase + (wn * 64 + q * 16 + lrow) * 80 + z * 32 + lcol);
                Bf[q * 2][0] = r0;     Bf[q * 2][1] = r2;
                Bf[q * 2 + 1][0] = r1; Bf[q * 2 + 1][1] = r3;
            }
            #pragma unroll
            for (int in = 0; in < 8; in++) mma_f8(acc[in], A, Bf[in]);
        }
    }
    const float SCL = 1.f / 131072.f;   // undo 4096 * 32
    #pragma unroll
    for (int hf = 0; hf < 2; hf++) {
        int s = s0 + wm * 16 + g + hf * 8;
        #pragma unroll
        for (int in = 0; in < 8; in++) {
            __nv_bfloat162 o = __floats2bfloat162_rn(acc[in][hf * 2] * SCL,
                                                     acc[in][hf * 2 + 1] * SCL);
            *(__nv_bfloat162*)&g_z[(size_t)s * FD + wn * 64 + in * 8 + 2 * tg] = o;
        }
    }
}

// ---- KW2A ----
__global__ void kw2a(const float* __restrict__ W2, const float* __restrict__ a) {
    int h = blockIdx.x, k = threadIdx.x;
    const float* w  = W2 + (size_t)h * FD * FD + (size_t)k * FD;
    const float* a2 = a + h * 2 * FD + FD;
    float acc = 0.f;
    #pragma unroll 8
    for (int f = 0; f < FD; f++) acc = fmaf(w[f], a2[f], acc);
    g_w2a[h * FD + k] = acc;
}

// ---- K1 ----
__global__ void k1_h1(const float* __restrict__ Rfeat, const float* __restrict__ W1,
                      const float* __restrict__ a) {
    int h = blockIdx.x / R_N, r = blockIdx.x % R_N, f = threadIdx.x;
    const float* w  = W1 + (size_t)h * FD * FD;
    const float* rf = Rfeat + r * FD;
    float acc = 0.f;
    #pragma unroll 8
    for (int k = 0; k < FD; k++) acc = fmaf(rf[k], w[k * FD + f], acc);
    g_h1[(h * R_N + r) * FD + f] = acc;
    __shared__ float sh[128];
    sh[f] = acc * a[h * 2 * FD + f];
    __syncthreads();
    for (int st = 64; st > 0; st >>= 1) {
        if (f < st) sh[f] += sh[f + st];
        __syncthreads();
    }
    if (f == 0) g_h1a[h * R_N + r] = sh[0];
}

// ---- K45: attention (Sfeat . w2a) + M partials = att^T @ Sfeat ----
__global__ __launch_bounds__(256) void k45_attv(const int* __restrict__ inter,
                                                const float* __restrict__ Sfeat) {
    const int h = blockIdx.y, tile = blockIdx.x, s0 = tile * 64;
    const int tid = threadIdx.x, lane = tid & 31, w = tid >> 5;
    __shared__ float attS[64][17];
    __shared__ float red[R_N * 128];
    float wv[4];
    #pragma unroll
    for (int i = 0; i < 4; i++) wv[i] = g_w2a[h * FD + lane + 32 * i];
    #pragma unroll
    for (int it = 0; it < 8; it++) {
        int sl = w * 8 + it;
        int s = s0 + sl;
        if (s < S_N) {
            const float* row = &Sfeat[(size_t)s * FD];
            float d = 0.f;
            #pragma unroll
            for (int i = 0; i < 4; i++) d = fmaf(row[lane + 32 * i], wv[i], d);
            #pragma unroll
            for (int o = 16; o > 0; o >>= 1) d += __shfl_xor_sync(0xffffffffu, d, o);
            float z = NEG;
            if (lane < R_N && inter[s * R_N + lane] > 0)
                z = lrelu(d + g_h1a[h * R_N + lane]);
            float mx = z;
            #pragma unroll
            for (int o = 8; o > 0; o >>= 1) mx = fmaxf(mx, __shfl_xor_sync(0xffffffffu, mx, o));
            float ex = (lane < R_N) ? expf(z - mx) : 0.f;
            float sm = ex;
            #pragma unroll
            for (int o = 8; o > 0; o >>= 1) sm += __shfl_xor_sync(0xffffffffu, sm, o);
            if (lane < R_N) {
                float av = ex / sm;
                attS[sl][lane] = av;
                g_att[((h * S_N) + s) * R_N + lane] = av;
            }
        } else if (lane < R_N) {
            attS[sl][lane] = 0.f;
        }
    }
    __syncthreads();
    const int f = tid & 127, half = tid >> 7;
    float acc[R_N];
    #pragma unroll
    for (int r = 0; r < R_N; r++) acc[r] = 0.f;
    const int base = half * 32;
    for (int si = 0; si < 32; si++) {
        int s = s0 + base + si;
        if (s >= S_N) break;
        float v = Sfeat[(size_t)s * FD + f];
        #pragma unroll
        for (int r = 0; r < R_N; r++) acc[r] = fmaf(attS[base + si][r], v, acc[r]);
    }
    if (half == 1) {
        #pragma unroll
        for (int r = 0; r < R_N; r++) red[r * 128 + f] = acc[r];
    }
    __syncthreads();
    if (half == 0) {
        #pragma unroll
        for (int r = 0; r < R_N; r++)
            g_vpart[((tile * H_N * R_N) + h * R_N + r) * FD + f] =
                acc[r] + red[r * 128 + f];
    }
}

// ---- K5r ----
__global__ void k5r() {
    int h = blockIdx.x >> 4, r = blockIdx.x & 15;
    int part = blockIdx.y, f = threadIdx.x;
    int c0 = part * 79;
    float t = 0.f;
    #pragma unroll 4
    for (int c = 0; c < 79; c++)
        t += g_vpart[(((c0 + c) * H_N * R_N) + h * R_N + r) * FD + f];
    g_vsum[((part * H_N + h) * R_N + r) * FD + f] = t;
}

// ---- K5m: vraw = M @ W2[h] ----
__global__ void k5m(const float* __restrict__ W2) {
    int h = blockIdx.x >> 4, r = blockIdx.x & 15;
    int f = threadIdx.x;
    __shared__ float M[128];
    M[f] = g_vsum[((0 * H_N + h) * R_N + r) * FD + f]
         + g_vsum[((1 * H_N + h) * R_N + r) * FD + f];
    __syncthreads();
    const float* w = W2 + (size_t)h * FD * FD;
    float acc = 0.f;
    #pragma unroll 8
    for (int k = 0; k < FD; k++) acc = fmaf(M[k], w[k * FD + f], acc);
    g_vraw[(h * R_N + r) * FD + f] = acc;
}

// ---- K5b2 ----
__global__ void k5b2(const float* __restrict__ g1, const float* __restrict__ b1) {
    int i = blockIdx.x * blockDim.x + threadIdx.x;
    if (i >= H_N * FD) return;
    int h = i / FD, f = i % FD;
    float x[R_N];
    float m = 0.f;
    #pragma unroll
    for (int r = 0; r < R_N; r++) {
        float t = g_vraw[(h * R_N + r) * FD + f];
        x[r] = t;
        m += t;
    }
    m *= (1.f / R_N);
    float var = 0.f;
    #pragma unroll
    for (int r = 0; r < R_N; r++) { float d = x[r] - m; var = fmaf(d, d, var); }
    var *= (1.f / R_N);
    float inv = rsqrtf(var + 1e-5f);
    float gg = g1[i], bb = b1[i];
    #pragma unroll
    for (int r = 0; r < R_N; r++)
        g_v[((h * R_N) + r) * FD + f] = lrelu((x[r] - m) * inv * gg + bb);
}

// ---- K6B: u_h = Z @ W2_h (bf16 mma, K=128) + fp32 InterRC + BN partials ----
// smem: zsh [128][136]bf16 @0 (34816) | wsh [128][136]bf16 @34816 |
//       attsh [128][17]f32 @69632 (8704) | h1sh [16][128]f32 @78336 (8192) = 86528
#define K6B_SMEM 86528
__global__ __launch_bounds__(256) void k6b(const float* __restrict__ W2) {
    extern __shared__ __align__(16) char sm6[];
    __nv_bfloat16 (*wsh)[136] = (__nv_bfloat16(*)[136])(sm6 + 34816);
    float (*attsh)[17] = (float(*)[17])(sm6 + 69632);
    float (*h1sh)[128] = (float(*)[128])(sm6 + 78336);

    const int h = blockIdx.y, tile = blockIdx.x, s0 = tile * 128;
    const int tid = threadIdx.x, lane = tid & 31, w = tid >> 5;
    const int wm = w >> 1, wn = w & 1;
    const int g = lane >> 2, tg = lane & 3;

    // Z tile via cp.async (128 rows x 256B)
    #pragma unroll
    for (int j = 0; j < 8; j++) {
        int idx = tid + j * 256;
        int row = idx >> 4, sg = idx & 15;
        CP16(su(sm6) + row * 272 + sg * 16, &g_z[(size_t)(s0 + row) * FD + sg * 8]);
    }
    CPCOMMIT;
    // W2 fp32 -> bf16 smem
    const float4* w4 = (const float4*)(W2 + (size_t)h * FD * FD);
    #pragma unroll
    for (int j = 0; j < 16; j++) {
        int idx = tid + j * 256;
        int row = idx >> 5, sg = idx & 31;
        float4 v = w4[idx];
        __nv_bfloat162 p0 = __floats2bfloat162_rn(v.x, v.y);
        __nv_bfloat162 p1 = __floats2bfloat162_rn(v.z, v.w);
        *(__nv_bfloat162*)&wsh[row][sg * 4] = p0;
        *(__nv_bfloat162*)&wsh[row][sg * 4 + 2] = p1;
    }
    for (int i = tid; i < 128 * R_N; i += 256) {
        int sl = i >> 4, r = i & 15;
        int s = s0 + sl;
        attsh[sl][r] = (s < S_N) ? g_att[((h * S_N) + s) * R_N + r] : 0.f;
    }
    for (int i = tid; i < R_N * FD; i += 256)
        h1sh[i >> 7][i & 127] = g_h1[h * R_N * FD + i];
    asm volatile("cp.async.wait_group 0;");
    __syncthreads();

    float acc[2][8][4] = {};
    const int lrow = lane & 15;
    #pragma unroll
    for (int kk = 0; kk < 8; kk++) {
        unsigned A[2][4];
        #pragma unroll
        for (int im = 0; im < 2; im++)
            ldmx4(A[im][0], A[im][1], A[im][2], A[im][3],
                  su(sm6) + (wm * 32 + im * 16 + lrow) * 272 + kk * 32 + (lane >> 4) * 16);
        unsigned Bf[8][2];
        #pragma unroll
        for (int q = 0; q < 4; q++) {
            unsigned r0, r1, r2, r3;
            ldmx4t(r0, r1, r2, r3,
                   su(sm6) + 34816 + (kk * 16 + lrow) * 272
                   + (wn * 64 + q * 16 + ((lane >> 4) << 3)) * 2);
            Bf[q * 2][0] = r0;     Bf[q * 2][1] = r1;
            Bf[q * 2 + 1][0] = r2; Bf[q * 2 + 1][1] = r3;
        }
        #pragma unroll
        for (int im = 0; im < 2; im++)
            #pragma unroll
            for (int in = 0; in < 8; in++)
                mma_bf16(acc[im][in], A[im], Bf[in]);
    }

    // InterRC in fp32
    const int sb = wm * 32 + g;
    const int fb = wn * 64 + 2 * tg;
    #pragma unroll
    for (int r = 0; r < R_N; r++) {
        float a00 = attsh[sb][r],      a01 = attsh[sb + 8][r];
        float a10 = attsh[sb + 16][r], a11 = attsh[sb + 24][r];
        #pragma unroll
        for (int in = 0; in < 8; in++) {
            float hv0 = h1sh[r][fb + in * 8];
            float hv1 = h1sh[r][fb + in * 8 + 1];
            acc[0][in][0] = fmaf(a00, hv0, acc[0][in][0]);
            acc[0][in][1] = fmaf(a00, hv1, acc[0][in][1]);
            acc[0][in][2] = fmaf(a01, hv0, acc[0][in][2]);
            acc[0][in][3] = fmaf(a01, hv1, acc[0][in][3]);
            acc[1][in][0] = fmaf(a10, hv0, acc[1][in][0]);
            acc[1][in][1] = fmaf(a10, hv1, acc[1][in][1]);
            acc[1][in][2] = fmaf(a11, hv0, acc[1][in][2]);
            acc[1][in][3] = fmaf(a11, hv1, acc[1][in][3]);
        }
    }
    // store u
    #pragma unroll
    for (int im = 0; im < 2; im++)
        #pragma unroll
        for (int hf = 0; hf < 2; hf++) {
            int s = s0 + wm * 32 + im * 16 + g + hf * 8;
            if (s < S_N) {
                float* up = &g_u[((size_t)h * S_N + s) * FD + fb];
                #pragma unroll
                for (int in = 0; in < 8; in++) {
                    float2 o = make_float2(acc[im][in][hf * 2], acc[im][in][hf * 2 + 1]);
                    *(float2*)(up + in * 8) = o;
                }
            }
        }
    // fused BN column partials
    __syncthreads();
    float* rs = (float*)sm6;
    float* rq = rs + 512;
    #pragma unroll
    for (int in = 0; in < 8; in++)
        #pragma unroll
        for (int half = 0; half < 2; half++) {
            float a0 = acc[0][in][half],     a1 = acc[0][in][2 + half];
            float a2 = acc[1][in][half],     a3 = acc[1][in][2 + half];
            float sm_ = a0 + a1 + a2 + a3;
            float sq_ = a0 * a0 + a1 * a1 + a2 * a2 + a3 * a3;
            #pragma unroll
            for (int o = 4; o <= 16; o <<= 1) {
                sm_ += __shfl_xor_sync(0xffffffffu, sm_, o);
                sq_ += __shfl_xor_sync(0xffffffffu, sq_, o);
            }
            if (lane < 4) {
                int f = wn * 64 + in * 8 + 2 * lane + half;
                rs[wm * 128 + f] = sm_;
                rq[wm * 128 + f] = sq_;
            }
        }
    __syncthreads();
    if (tid < 128) {
        float s4 = rs[tid] + rs[128 + tid] + rs[256 + tid] + rs[384 + tid];
        float q4 = rq[tid] + rq[128 + tid] + rq[256 + tid] + rq[384 + tid];
        g_upsum[tile * H_N * FD + h * FD + tid] = s4;
        g_upsq [tile * H_N * FD + h * FD + tid] = q4;
    }
}

// ---- K7b ----
__global__ void k7b_bnu(const float* __restrict__ g2, const float* __restrict__ b2) {
    int i = blockIdx.x * blockDim.x + threadIdx.x;
    if (i >= H_N * FD) return;
    float sm = 0.f, sq = 0.f;
    #pragma unroll 4
    for (int c = 0; c < 79; c++) {
        sm += g_upsum[c * H_N * FD + i];
        sq += g_upsq [c * H_N * FD + i];
    }
    float mean = sm / (float)S_N;
    float var = sq / (float)S_N - mean * mean;
    float al = g2[i] * rsqrtf(var + 1e-5f);
    g_alpha[i] = al;
    g_beta[i]  = b2[i] - mean * al;
}

// ---- K8 ----
__global__ void k8_out(const int* __restrict__ inter, const float* __restrict__ outW,
                       float* __restrict__ out) {
    int s = blockIdx.x * 8 + (threadIdx.x >> 5);
    int lane = threadIdx.x & 31;
    if (s >= S_N) return;
    float un[H_N][4];
    #pragma unroll
    for (int h = 0; h < H_N; h++)
        #pragma unroll
        for (int i = 0; i < 4; i++) {
            int f = lane + 32 * i;
            float x = g_u[((size_t)h * S_N + s) * FD + f];
            un[h][i] = lrelu(fmaf(x, g_alpha[h * FD + f], g_beta[h * FD + f]));
        }
    float hf = 0.f;
    #pragma unroll
    for (int h = 0; h < H_N; h++)
        for (int r = 0; r < R_N; r++) {
            float d = 0.f;
            #pragma unroll
            for (int i = 0; i < 4; i++) {
                int f = lane + 32 * i;
                d = fmaf(un[h][i], g_v[((h * R_N) + r) * FD + f], d);
            }
            #pragma unroll
            for (int o = 16; o > 0; o >>= 1) d += __shfl_xor_sync(0xffffffffu, d, o);
            float ho = elu(d);
            if (lane < C_N) hf = fmaf(ho, outW[(h * R_N + r) * C_N + lane], hf);
        }
    int adj = (lane < R_N) ? inter[s * R_N + lane] : 0;
    unsigned m = __ballot_sync(0xffffffffu, (lane < R_N) && adj > 0);
    int deg = __popc(m);
    float att = (deg > 0) ? (adj > 0 ? 1.f / (float)deg : 0.f) : (1.f / (float)R_N);
    float t = att * hf;
    t = elu(t);
    t = elu(t);
    float z = (lane < C_N) ? t : -3.4e38f;
    float mx = z;
    #pragma unroll
    for (int o = 8; o > 0; o >>= 1) mx = fmaxf(mx, __shfl_xor_sync(0xffffffffu, mx, o));
    float ex = (lane < C_N) ? expf(z - mx) : 0.f;
    float sm = ex;
    #pragma unroll
    for (int o = 8; o > 0; o >>= 1) sm += __shfl_xor_sync(0xffffffffu, sm, o);
    if (lane < C_N) out[s * C_N + lane] = (z - mx) - logf(sm);
}

// ---- launch ----
extern "C" void kernel_launch(void* const* d_in, const int* in_sizes, int n_in,
                              void* d_out, int out_size) {
    const int*   inter = (const int*)d_in[0];
    const int*   city  = (const int*)d_in[1];
    const int*   prov  = (const int*)d_in[2];
    const int*   src   = (const int*)d_in[3];
    const float* Sfeat = (const float*)d_in[4];
    const float* Rfeat = (const float*)d_in[5];
    const float* W1    = (const float*)d_in[6];
    const float* W2    = (const float*)d_in[7];
    const float* a     = (const float*)d_in[8];
    const float* bn1g  = (const float*)d_in[11];
    const float* bn1b  = (const float*)d_in[12];
    const float* bn2g  = (const float*)d_in[13];
    const float* bn2b  = (const float*)d_in[14];
    const float* outW  = (const float*)d_in[15];
    float* out = (float*)d_out;

    cudaFuncSetAttribute(kZ,  cudaFuncAttributeMaxDynamicSharedMemorySize, KZ_SMEM);
    cudaFuncSetAttribute(k6b, cudaFuncAttributeMaxDynamicSharedMemorySize, K6B_SMEM);

    k3_bits<<<B_N, 256>>>(city, prov, src);
    k3w_t8<<<dim3(SP / 32, B_N / 256), 256>>>();
    ksgT8<<<64, 256>>>(Sfeat, src);
    kZ<<<SP / 64, 256, KZ_SMEM>>>();                  // profiled slot #4
    kw2a<<<H_N, 128>>>(W2, a);
    k1_h1<<<H_N * R_N, 128>>>(Rfeat, W1, a);
    k45_attv<<<dim3(158, H_N), 256>>>(inter, Sfeat);
    k5r<<<dim3(64, 2), 128>>>();
    k5m<<<H_N * R_N, 128>>>(W2);
    k5b2<<<(H_N * FD + 127) / 128, 128>>>(bn1g, bn1b);
    k6b<<<dim3(79, H_N), 256, K6B_SMEM>>>(W2);
    k7b_bnu<<<(H_N * FD + 127) / 128, 128>>>(bn2g, bn2b);
    k8_out<<<(S_N + 7) / 8, 256>>>(inter, outW, out);
}